// round 3
// baseline (speedup 1.0000x reference)
#include <cuda_runtime.h>
#include <math.h>

// ---------------- problem constants ----------------
#define BB    2
#define SS    1024
#define TOK   2048          // B*S
#define DIM   1024
#define QKVD  3072
#define NHEAD 16
#define HDIM  64
#define NEXP  8
#define FDIM  4096
#define NSLOT 4096          // TOK * top_k

// ---------------- device scratch (no allocs allowed) ----------------
__device__ __align__(128) float g_qkv [(size_t)TOK * QKVD];   // 25 MB
__device__ __align__(128) float g_attn[(size_t)TOK * DIM];    // 8 MB
__device__ __align__(128) float g_proj[(size_t)TOK * DIM];    // 8 MB
__device__ __align__(128) float g_x1  [(size_t)TOK * DIM];    // 8 MB
__device__ __align__(128) float g_h   [(size_t)NSLOT * FDIM]; // 64 MB (expert hidden)
__device__ __align__(128) float g_moe2[(size_t)NSLOT * DIM];  // 16 MB (per-slot expert out)
__device__ int   g_tidx[NSLOT];
__device__ float g_tprob[NSLOT];
__device__ float g_usage[NEXP];
__device__ int   g_count[NEXP];
__device__ int   g_off[NEXP];
__device__ int   g_fill[NEXP];
__device__ int   g_list[NSLOT];

__device__ __forceinline__ float gelu_f(float x) {
    return 0.5f * x * (1.0f + erff(x * 0.70710678118654752f));
}

// ---------------- init (re-zero per replay) ----------------
__global__ void k_init() {
    int i = threadIdx.x;
    if (i < NEXP) { g_usage[i] = 0.f; g_count[i] = 0; g_fill[i] = 0; }
}

// ---------------- NT SGEMM: C[m,n] = sum_k A[m,k]*B[n,k] (+bias, epilogues) ----
// MODE 0: plain + bias
// MODE 1: A rows gathered via g_list (token = slot>>1), gelu(acc+bias),
//         C row = g_off[e] + m  (contiguous per expert)
// MODE 2: A rows = g_off[e]+m (contiguous), (acc+bias)*prob, scatter C row = slot
template<int MODE>
__global__ void __launch_bounds__(256, 2) gemm_nt(
    const float* __restrict__ A, const float* __restrict__ B,
    const float* __restrict__ bias, float* __restrict__ C,
    int M, int N, int K, long strideBe, int strideBiasE)
{
    const int BM = 128, BN = 128, BK = 16;
    __shared__ float As[BK][BM + 4];
    __shared__ float Bs[BK][BN + 4];

    int tid   = threadIdx.x;
    int mBase = blockIdx.y * BM;
    int nBase = blockIdx.x * BN;

    int count = M;
    int off   = 0;
    const int* lst = 0;
    if (MODE != 0) {
        int e = blockIdx.z;
        count = g_count[e];
        if (mBase >= count) return;
        off  = g_off[e];
        B    += (long)e * strideBe;
        bias += (long)e * strideBiasE;
        lst  = g_list + off;
    }

    // loader: each thread loads 8 contiguous K-floats of one row (A and B)
    int lRow  = tid >> 1;           // 0..127
    int lK8   = (tid & 1) << 3;     // 0 or 8
    int mIdxL = mBase + lRow;
    long aRow;
    if (MODE == 0)      aRow = mIdxL;
    else if (MODE == 1) aRow = (long)(lst[min(mIdxL, count - 1)] >> 1);
    else                aRow = (long)off + min(mIdxL, count - 1);
    const float* Ap = A + aRow * (long)K + lK8;
    const float* Bp = B + (long)(nBase + lRow) * K + lK8;

    float acc[8][8];
    #pragma unroll
    for (int i = 0; i < 8; i++)
        #pragma unroll
        for (int j = 0; j < 8; j++) acc[i][j] = 0.f;

    int tx = tid & 15, ty = tid >> 4;

    for (int kt = 0; kt < K; kt += BK) {
        float4 a0 = *(const float4*)(Ap + kt);
        float4 a1 = *(const float4*)(Ap + kt + 4);
        float4 b0 = *(const float4*)(Bp + kt);
        float4 b1 = *(const float4*)(Bp + kt + 4);
        As[lK8+0][lRow] = a0.x; As[lK8+1][lRow] = a0.y;
        As[lK8+2][lRow] = a0.z; As[lK8+3][lRow] = a0.w;
        As[lK8+4][lRow] = a1.x; As[lK8+5][lRow] = a1.y;
        As[lK8+6][lRow] = a1.z; As[lK8+7][lRow] = a1.w;
        Bs[lK8+0][lRow] = b0.x; Bs[lK8+1][lRow] = b0.y;
        Bs[lK8+2][lRow] = b0.z; Bs[lK8+3][lRow] = b0.w;
        Bs[lK8+4][lRow] = b1.x; Bs[lK8+5][lRow] = b1.y;
        Bs[lK8+6][lRow] = b1.z; Bs[lK8+7][lRow] = b1.w;
        __syncthreads();
        #pragma unroll
        for (int k = 0; k < BK; k++) {
            float av[8], bv[8];
            #pragma unroll
            for (int i = 0; i < 4; i++) {
                av[i]     = As[k][ty * 4 + i];
                av[4 + i] = As[k][64 + ty * 4 + i];
            }
            #pragma unroll
            for (int j = 0; j < 4; j++) {
                bv[j]     = Bs[k][tx * 4 + j];
                bv[4 + j] = Bs[k][64 + tx * 4 + j];
            }
            #pragma unroll
            for (int i = 0; i < 8; i++)
                #pragma unroll
                for (int j = 0; j < 8; j++)
                    acc[i][j] += av[i] * bv[j];
        }
        __syncthreads();
    }

    #pragma unroll
    for (int ii = 0; ii < 2; ii++) {
        #pragma unroll
        for (int i = 0; i < 4; i++) {
            int r    = ii * 64 + ty * 4 + i;
            int mIdx = mBase + r;
            if (MODE != 0 && mIdx >= count) continue;
            long cRow; float scl = 1.f;
            if (MODE == 0)      cRow = mIdx;
            else if (MODE == 1) cRow = (long)off + mIdx;
            else { int slot = lst[mIdx]; cRow = slot; scl = g_tprob[slot]; }
            float* Cr = C + cRow * (long)N + nBase;
            #pragma unroll
            for (int jj = 0; jj < 2; jj++) {
                #pragma unroll
                for (int j = 0; j < 4; j++) {
                    int c   = jj * 64 + tx * 4 + j;
                    float v = acc[ii * 4 + i][jj * 4 + j] + bias[nBase + c];
                    if (MODE == 1) v = gelu_f(v);
                    v *= scl;
                    Cr[c] = v;
                }
            }
        }
    }
}

// ---------------- flash attention (fp32, 64q x 64k tiles, HD=64) -------------
__global__ void __launch_bounds__(256) attn_kernel(
    const float* __restrict__ qkv, float* __restrict__ out)
{
    extern __shared__ float sm[];
    const int LD = 65;
    float* Qs = sm;
    float* Ks = sm + 64 * LD;
    float* Vs = sm + 2 * 64 * LD;
    float* Ps = sm + 3 * 64 * LD;

    int tid = threadIdx.x;
    int bh  = blockIdx.y;
    int b   = bh >> 4, h = bh & 15;
    int q0  = blockIdx.x * 64;
    const float* qb = qkv + (long)b * SS * QKVD + h * HDIM;
    const float* kb = qb + DIM;
    const float* vb = qb + 2 * DIM;

    int lr = tid >> 2;               // 0..63 (row)
    int lc = (tid & 3) * 4;          // col base

    // load Q tile (row-major, padded)
    #pragma unroll
    for (int u = 0; u < 4; u++) {
        int d = lc + u * 16;
        float4 v = *(const float4*)(qb + (long)(q0 + lr) * QKVD + d);
        Qs[lr * LD + d + 0] = v.x; Qs[lr * LD + d + 1] = v.y;
        Qs[lr * LD + d + 2] = v.z; Qs[lr * LD + d + 3] = v.w;
    }

    int tx = tid & 15, ty = tid >> 4;
    float m_i[4], l_i[4], o[4][4];
    #pragma unroll
    for (int i = 0; i < 4; i++) {
        m_i[i] = -1e30f; l_i[i] = 0.f;
        #pragma unroll
        for (int j = 0; j < 4; j++) o[i][j] = 0.f;
    }

    for (int kt = 0; kt < SS; kt += 64) {
        __syncthreads();
        #pragma unroll
        for (int u = 0; u < 4; u++) {
            int d = lc + u * 16;
            float4 kv = *(const float4*)(kb + (long)(kt + lr) * QKVD + d);
            float4 vv = *(const float4*)(vb + (long)(kt + lr) * QKVD + d);
            Ks[lr * LD + d + 0] = kv.x; Ks[lr * LD + d + 1] = kv.y;
            Ks[lr * LD + d + 2] = kv.z; Ks[lr * LD + d + 3] = kv.w;
            Vs[lr * LD + d + 0] = vv.x; Vs[lr * LD + d + 1] = vv.y;
            Vs[lr * LD + d + 2] = vv.z; Vs[lr * LD + d + 3] = vv.w;
        }
        __syncthreads();

        // scores S = Q K^T
        float s[4][4];
        #pragma unroll
        for (int i = 0; i < 4; i++)
            #pragma unroll
            for (int j = 0; j < 4; j++) s[i][j] = 0.f;
        #pragma unroll 8
        for (int d = 0; d < 64; d++) {
            float a[4], bq[4];
            #pragma unroll
            for (int i = 0; i < 4; i++) a[i]  = Qs[(ty * 4 + i) * LD + d];
            #pragma unroll
            for (int j = 0; j < 4; j++) bq[j] = Ks[(tx * 4 + j) * LD + d];
            #pragma unroll
            for (int i = 0; i < 4; i++)
                #pragma unroll
                for (int j = 0; j < 4; j++) s[i][j] += a[i] * bq[j];
        }

        // online softmax (rows shared by the 16 tx-lanes of this ty group)
        #pragma unroll
        for (int i = 0; i < 4; i++) {
            float rm = -1e30f;
            #pragma unroll
            for (int j = 0; j < 4; j++) { s[i][j] *= 0.125f; rm = fmaxf(rm, s[i][j]); }
            #pragma unroll
            for (int o2 = 8; o2 >= 1; o2 >>= 1)
                rm = fmaxf(rm, __shfl_xor_sync(0xffffffffu, rm, o2));
            float mn    = fmaxf(m_i[i], rm);
            float alpha = expf(m_i[i] - mn);
            m_i[i] = mn;
            float rs = 0.f;
            #pragma unroll
            for (int j = 0; j < 4; j++) { s[i][j] = expf(s[i][j] - mn); rs += s[i][j]; }
            #pragma unroll
            for (int o2 = 8; o2 >= 1; o2 >>= 1)
                rs += __shfl_xor_sync(0xffffffffu, rs, o2);
            l_i[i] = l_i[i] * alpha + rs;
            #pragma unroll
            for (int j = 0; j < 4; j++) {
                o[i][j] *= alpha;
                Ps[(ty * 4 + i) * LD + tx * 4 + j] = s[i][j];
            }
        }
        __syncthreads();

        // O += P V
        #pragma unroll 8
        for (int c = 0; c < 64; c++) {
            float a[4], bv[4];
            #pragma unroll
            for (int i = 0; i < 4; i++) a[i]  = Ps[(ty * 4 + i) * LD + c];
            #pragma unroll
            for (int j = 0; j < 4; j++) bv[j] = Vs[c * LD + tx * 4 + j];
            #pragma unroll
            for (int i = 0; i < 4; i++)
                #pragma unroll
                for (int j = 0; j < 4; j++) o[i][j] += a[i] * bv[j];
        }
    }

    #pragma unroll
    for (int i = 0; i < 4; i++) {
        float inv = 1.f / l_i[i];
        long row  = (long)b * SS + q0 + ty * 4 + i;
        #pragma unroll
        for (int j = 0; j < 4; j++)
            out[row * DIM + h * HDIM + tx * 4 + j] = o[i][j] * inv;
    }
}

// ---------------- residual + LayerNorm (x = LN(a + b)) -----------------------
__global__ void __launch_bounds__(256) ln_res_kernel(
    const float* __restrict__ a, const float* __restrict__ b,
    const float* __restrict__ g, const float* __restrict__ bt,
    float* __restrict__ out)
{
    long t  = blockIdx.x;
    int tid = threadIdx.x;
    float4 va = ((const float4*)(a + t * DIM))[tid];
    float4 vb = ((const float4*)(b + t * DIM))[tid];
    float v[4] = { va.x + vb.x, va.y + vb.y, va.z + vb.z, va.w + vb.w };
    float s1 = v[0] + v[1] + v[2] + v[3];
    float s2 = v[0]*v[0] + v[1]*v[1] + v[2]*v[2] + v[3]*v[3];
    #pragma unroll
    for (int o2 = 16; o2 >= 1; o2 >>= 1) {
        s1 += __shfl_xor_sync(0xffffffffu, s1, o2);
        s2 += __shfl_xor_sync(0xffffffffu, s2, o2);
    }
    __shared__ float r1[8], r2[8], mv[2];
    if ((tid & 31) == 0) { r1[tid >> 5] = s1; r2[tid >> 5] = s2; }
    __syncthreads();
    if (tid == 0) {
        float A = 0.f, Bq = 0.f;
        #pragma unroll
        for (int w = 0; w < 8; w++) { A += r1[w]; Bq += r2[w]; }
        float mean = A * (1.f / DIM);
        float var  = Bq * (1.f / DIM) - mean * mean;
        mv[0] = mean; mv[1] = rsqrtf(var + 1e-5f);
    }
    __syncthreads();
    float mean = mv[0], rstd = mv[1];
    float4 gg = ((const float4*)g)[tid];
    float4 bbv = ((const float4*)bt)[tid];
    float4 ov;
    ov.x = (v[0] - mean) * rstd * gg.x + bbv.x;
    ov.y = (v[1] - mean) * rstd * gg.y + bbv.y;
    ov.z = (v[2] - mean) * rstd * gg.z + bbv.z;
    ov.w = (v[3] - mean) * rstd * gg.w + bbv.w;
    ((float4*)(out + t * DIM))[tid] = ov;
}

// ---------------- combine MoE slots + residual + LN2 -> d_out ----------------
__global__ void __launch_bounds__(256) ln2_kernel(
    const float* __restrict__ x1, const float* __restrict__ moe2,
    const float* __restrict__ g, const float* __restrict__ bt,
    float* __restrict__ out)
{
    long t  = blockIdx.x;
    int tid = threadIdx.x;
    float4 va = ((const float4*)(x1   + t * DIM))[tid];
    float4 vb = ((const float4*)(moe2 + (2 * t)     * DIM))[tid];
    float4 vc = ((const float4*)(moe2 + (2 * t + 1) * DIM))[tid];
    float v[4] = { va.x + vb.x + vc.x, va.y + vb.y + vc.y,
                   va.z + vb.z + vc.z, va.w + vb.w + vc.w };
    float s1 = v[0] + v[1] + v[2] + v[3];
    float s2 = v[0]*v[0] + v[1]*v[1] + v[2]*v[2] + v[3]*v[3];
    #pragma unroll
    for (int o2 = 16; o2 >= 1; o2 >>= 1) {
        s1 += __shfl_xor_sync(0xffffffffu, s1, o2);
        s2 += __shfl_xor_sync(0xffffffffu, s2, o2);
    }
    __shared__ float r1[8], r2[8], mv[2];
    if ((tid & 31) == 0) { r1[tid >> 5] = s1; r2[tid >> 5] = s2; }
    __syncthreads();
    if (tid == 0) {
        float A = 0.f, Bq = 0.f;
        #pragma unroll
        for (int w = 0; w < 8; w++) { A += r1[w]; Bq += r2[w]; }
        float mean = A * (1.f / DIM);
        float var  = Bq * (1.f / DIM) - mean * mean;
        mv[0] = mean; mv[1] = rsqrtf(var + 1e-5f);
    }
    __syncthreads();
    float mean = mv[0], rstd = mv[1];
    float4 gg = ((const float4*)g)[tid];
    float4 bbv = ((const float4*)bt)[tid];
    float4 ov;
    ov.x = (v[0] - mean) * rstd * gg.x + bbv.x;
    ov.y = (v[1] - mean) * rstd * gg.y + bbv.y;
    ov.z = (v[2] - mean) * rstd * gg.z + bbv.z;
    ov.w = (v[3] - mean) * rstd * gg.w + bbv.w;
    ((float4*)(out + t * DIM))[tid] = ov;
}

// ---------------- gate: logits, softmax usage, top-2 -------------------------
__global__ void __launch_bounds__(256) gate_kernel(
    const float* __restrict__ x, const float* __restrict__ gw,
    const float* __restrict__ gb)
{
    int t = blockIdx.x;
    int w = threadIdx.x >> 5, lane = threadIdx.x & 31;
    const float* xr = x + (long)t * DIM;
    const float* wr = gw + w * DIM;
    float s = 0.f;
    for (int d = lane; d < DIM; d += 32) s += xr[d] * wr[d];
    #pragma unroll
    for (int o2 = 16; o2 >= 1; o2 >>= 1) s += __shfl_xor_sync(0xffffffffu, s, o2);
    __shared__ float lg[NEXP];
    if (lane == 0) lg[w] = s + gb[w];
    __syncthreads();
    if (threadIdx.x == 0) {
        float mx = lg[0];
        #pragma unroll
        for (int e = 1; e < NEXP; e++) mx = fmaxf(mx, lg[e]);
        float ex[NEXP], sum = 0.f;
        #pragma unroll
        for (int e = 0; e < NEXP; e++) { ex[e] = expf(lg[e] - mx); sum += ex[e]; }
        float inv = 1.f / sum;
        #pragma unroll
        for (int e = 0; e < NEXP; e++) atomicAdd(&g_usage[e], ex[e] * inv);
        // top-2 (strict >, matching lax.top_k tie-break to lower index)
        int e0 = 0;
        #pragma unroll
        for (int e = 1; e < NEXP; e++) if (lg[e] > lg[e0]) e0 = e;
        int e1 = -1;
        #pragma unroll
        for (int e = 0; e < NEXP; e++)
            if (e != e0 && (e1 < 0 || lg[e] > lg[e1])) e1 = e;
        float z  = expf(lg[e1] - lg[e0]);
        float p0 = 1.f / (1.f + z);
        g_tidx[2 * t]     = e0;  g_tidx[2 * t + 1]  = e1;
        g_tprob[2 * t]    = p0;  g_tprob[2 * t + 1] = z * p0;
        atomicAdd(&g_count[e0], 1);
        atomicAdd(&g_count[e1], 1);
    }
}

__global__ void k_offsets() {
    if (threadIdx.x == 0) {
        int a = 0;
        for (int e = 0; e < NEXP; e++) { g_off[e] = a; a += g_count[e]; }
    }
}

__global__ void k_fill() {
    int t = blockIdx.x * blockDim.x + threadIdx.x;
    if (t < TOK) {
        #pragma unroll
        for (int k = 0; k < 2; k++) {
            int e   = g_tidx[2 * t + k];
            int pos = atomicAdd(&g_fill[e], 1);
            g_list[g_off[e] + pos] = 2 * t + k;
        }
    }
}

__global__ void k_aux(float* out) {
    float s = 0.f;
    #pragma unroll
    for (int e = 0; e < NEXP; e++) {
        float u = g_usage[e] * (1.f / TOK);
        s += u * u;
    }
    out[(size_t)TOK * DIM] = (float)NEXP * s;
}

// ---------------- launch ----------------
extern "C" void kernel_launch(void* const* d_in, const int* in_sizes, int n_in,
                              void* d_out, int out_size)
{
    (void)in_sizes; (void)n_in;
    const float* src  = (const float*)d_in[0];
    const float* ipw  = (const float*)d_in[1];
    const float* ipb  = (const float*)d_in[2];
    const float* outw = (const float*)d_in[3];
    const float* outb = (const float*)d_in[4];
    const float* gw   = (const float*)d_in[5];
    const float* gb   = (const float*)d_in[6];
    const float* w1   = (const float*)d_in[7];
    const float* b1   = (const float*)d_in[8];
    const float* w2   = (const float*)d_in[9];
    const float* b2   = (const float*)d_in[10];
    const float* ln1g = (const float*)d_in[11];
    const float* ln1b = (const float*)d_in[12];
    const float* ln2g = (const float*)d_in[13];
    const float* ln2b = (const float*)d_in[14];
    float* out = (float*)d_out;

    float *p_qkv, *p_attn, *p_proj, *p_x1, *p_h, *p_moe2;
    cudaGetSymbolAddress((void**)&p_qkv,  g_qkv);
    cudaGetSymbolAddress((void**)&p_attn, g_attn);
    cudaGetSymbolAddress((void**)&p_proj, g_proj);
    cudaGetSymbolAddress((void**)&p_x1,   g_x1);
    cudaGetSymbolAddress((void**)&p_h,    g_h);
    cudaGetSymbolAddress((void**)&p_moe2, g_moe2);

    const int ATTN_SMEM = 4 * 64 * 65 * (int)sizeof(float); // 66560 B
    cudaFuncSetAttribute(attn_kernel,
                         cudaFuncAttributeMaxDynamicSharedMemorySize, ATTN_SMEM);

    // 0) zero per-replay counters
    k_init<<<1, 32>>>();

    // 1) QKV projection: (2048 x 3072) = src @ in_proj_w^T + b
    gemm_nt<0><<<dim3(QKVD / 128, TOK / 128, 1), 256>>>(
        src, ipw, ipb, p_qkv, TOK, QKVD, DIM, 0, 0);

    // 2) attention -> g_attn (B,S,D)
    attn_kernel<<<dim3(SS / 64, BB * NHEAD), 256, ATTN_SMEM>>>(p_qkv, p_attn);

    // 3) output projection
    gemm_nt<0><<<dim3(DIM / 128, TOK / 128, 1), 256>>>(
        p_attn, outw, outb, p_proj, TOK, DIM, DIM, 0, 0);

    // 4) x1 = LN(src + attn_out)
    ln_res_kernel<<<TOK, 256>>>(p_proj, src, ln1g, ln1b, p_x1);

    // 5) gating: top-2 + usage
    gate_kernel<<<TOK, 256>>>(p_x1, gw, gb);
    k_offsets<<<1, 32>>>();
    k_fill<<<TOK / 256, 256>>>();

    // 6) expert GEMM1: h = gelu(x1 @ w1[e]^T + b1[e])  (gathered rows)
    gemm_nt<1><<<dim3(FDIM / 128, TOK / 128, NEXP), 256>>>(
        p_x1, w1, b1, p_h, TOK, FDIM, DIM, (long)FDIM * DIM, FDIM);

    // 7) expert GEMM2: eo = (h @ w2[e]^T + b2[e]) * prob  (scatter to slots)
    gemm_nt<2><<<dim3(DIM / 128, TOK / 128, NEXP), 256>>>(
        p_h, w2, b2, p_moe2, TOK, DIM, FDIM, (long)DIM * FDIM, DIM);

    // 8) out = LN(x1 + moe_out)
    ln2_kernel<<<TOK, 256>>>(p_x1, p_moe2, ln2g, ln2b, out);

    // 9) aux loss scalar
    if (out_size > TOK * DIM) k_aux<<<1, 1>>>(out);
}

// round 7
// speedup vs baseline: 1.6981x; 1.6981x over previous
#include <cuda_runtime.h>
#include <cuda_bf16.h>
#include <math.h>
#include <stdint.h>

// ---------------- problem constants ----------------
#define BB    2
#define SS    1024
#define TOK   2048          // B*S
#define DIM   1024
#define QKVD  3072
#define NHEAD 16
#define HDIM  64
#define NEXP  8
#define FDIM  4096
#define NSLOT 4096          // TOK * top_k

// ---------------- device scratch (no allocs allowed) ----------------
__device__ __align__(128) float g_qkv [(size_t)TOK * QKVD];   // fp32 (attn reads)
__device__ __align__(128) float g_proj[(size_t)TOK * DIM];
__device__ __align__(128) float g_x1  [(size_t)TOK * DIM];
__device__ __align__(128) float g_moe2[(size_t)NSLOT * DIM];

// hi/lo bf16 operand planes
__device__ __align__(128) __nv_bfloat16 g_srcH [(size_t)TOK * DIM];
__device__ __align__(128) __nv_bfloat16 g_srcL [(size_t)TOK * DIM];
__device__ __align__(128) __nv_bfloat16 g_attnH[(size_t)TOK * DIM];
__device__ __align__(128) __nv_bfloat16 g_attnL[(size_t)TOK * DIM];
__device__ __align__(128) __nv_bfloat16 g_x1H  [(size_t)TOK * DIM];
__device__ __align__(128) __nv_bfloat16 g_x1L  [(size_t)TOK * DIM];
__device__ __align__(128) __nv_bfloat16 g_hH   [(size_t)NSLOT * FDIM];
__device__ __align__(128) __nv_bfloat16 g_hL   [(size_t)NSLOT * FDIM];
__device__ __align__(128) __nv_bfloat16 g_ipwH [(size_t)QKVD * DIM];
__device__ __align__(128) __nv_bfloat16 g_ipwL [(size_t)QKVD * DIM];
__device__ __align__(128) __nv_bfloat16 g_outwH[(size_t)DIM * DIM];
__device__ __align__(128) __nv_bfloat16 g_outwL[(size_t)DIM * DIM];
__device__ __align__(128) __nv_bfloat16 g_w1H  [(size_t)NEXP * FDIM * DIM];
__device__ __align__(128) __nv_bfloat16 g_w1L  [(size_t)NEXP * FDIM * DIM];
__device__ __align__(128) __nv_bfloat16 g_w2H  [(size_t)NEXP * DIM * FDIM];
__device__ __align__(128) __nv_bfloat16 g_w2L  [(size_t)NEXP * DIM * FDIM];

__device__ int   g_tidx[NSLOT];
__device__ float g_tprob[NSLOT];
__device__ float g_usage[NEXP];
__device__ int   g_count[NEXP];
__device__ int   g_off[NEXP];
__device__ int   g_fill[NEXP];
__device__ int   g_list[NSLOT];

__device__ __forceinline__ float gelu_f(float x) {
    return 0.5f * x * (1.0f + erff(x * 0.70710678118654752f));
}

// ---------------- PTX helpers (all compute_103-legal) ----------------
__device__ __forceinline__ uint32_t smem_u32(const void* p) {
    uint32_t a;
    asm("{ .reg .u64 t; cvta.to.shared.u64 t, %1; cvt.u32.u64 %0, t; }"
        : "=r"(a) : "l"(p));
    return a;
}

#define CP16(dst, src) \
    asm volatile("cp.async.cg.shared.global [%0], [%1], 16;" \
                 :: "r"(dst), "l"(src) : "memory")
#define CPCOMMIT()  asm volatile("cp.async.commit_group;" ::: "memory")
#define CPWAIT0()   asm volatile("cp.async.wait_group 0;" ::: "memory")
#define CPWAIT1()   asm volatile("cp.async.wait_group 1;" ::: "memory")

#define LDSM4(R, addr) \
    asm volatile("ldmatrix.sync.aligned.m8n8.x4.shared.b16 {%0,%1,%2,%3}, [%4];" \
        : "=r"((R)[0]), "=r"((R)[1]), "=r"((R)[2]), "=r"((R)[3]) : "r"(addr))

__device__ __forceinline__ void mma16816(float* c, const uint32_t* a,
                                         uint32_t b0, uint32_t b1) {
    asm volatile(
        "mma.sync.aligned.m16n8k16.row.col.f32.bf16.bf16.f32 "
        "{%0,%1,%2,%3}, {%4,%5,%6,%7}, {%8,%9}, {%0,%1,%2,%3};"
        : "+f"(c[0]), "+f"(c[1]), "+f"(c[2]), "+f"(c[3])
        : "r"(a[0]), "r"(a[1]), "r"(a[2]), "r"(a[3]), "r"(b0), "r"(b1));
}

// ---------------- init (re-zero per replay) ----------------
__global__ void k_init() {
    int i = threadIdx.x;
    if (i < NEXP) { g_usage[i] = 0.f; g_count[i] = 0; g_fill[i] = 0; }
}

// ---------------- fp32 -> (hi, lo) bf16 planes ----------------
__global__ void __launch_bounds__(256) k_conv(
    const float* __restrict__ x, __nv_bfloat16* __restrict__ hi,
    __nv_bfloat16* __restrict__ lo, long n4)
{
    long i = (long)blockIdx.x * blockDim.x + threadIdx.x;
    if (i >= n4) return;
    float4 v = ((const float4*)x)[i];
    __nv_bfloat16 h0 = __float2bfloat16_rn(v.x);
    __nv_bfloat16 h1 = __float2bfloat16_rn(v.y);
    __nv_bfloat16 h2 = __float2bfloat16_rn(v.z);
    __nv_bfloat16 h3 = __float2bfloat16_rn(v.w);
    __nv_bfloat162 H0; H0.x = h0; H0.y = h1;
    __nv_bfloat162 H1; H1.x = h2; H1.y = h3;
    __nv_bfloat162 L0, L1;
    L0.x = __float2bfloat16_rn(v.x - __bfloat162float(h0));
    L0.y = __float2bfloat16_rn(v.y - __bfloat162float(h1));
    L1.x = __float2bfloat16_rn(v.z - __bfloat162float(h2));
    L1.y = __float2bfloat16_rn(v.w - __bfloat162float(h3));
    ((__nv_bfloat162*)hi)[2 * i]     = H0;
    ((__nv_bfloat162*)hi)[2 * i + 1] = H1;
    ((__nv_bfloat162*)lo)[2 * i]     = L0;
    ((__nv_bfloat162*)lo)[2 * i + 1] = L1;
}

// =====================================================================
// bf16-split NT GEMM via mma.sync: C[m,n] = sum_k A[m,k]*B[n,k]
//   tile 128x128x32, 8 warps (2m x 4n), hi/lo planes, cp.async double buffer
// MODE 0: C fp32 = acc + bias
// MODE 1: A rows gathered via g_list (token=slot>>1); gelu(acc+bias) ->
//         hi/lo bf16 planes at row g_off[e]+m
// MODE 2: A rows = g_off[e]+m; (acc+bias)*prob -> fp32 scatter to row slot
// =====================================================================
#define TSB   80            // smem row stride bytes (64 data + 16 pad)
#define PL    10240         // one plane: 128 rows * 80B
#define BUFB  40960         // 4 planes (Ahi, Alo, Bhi, Blo)
#define SM_BIAS  81920      // after 2 buffers
#define SM_TOTAL (SM_BIAS + 512)

template<int MODE>
__global__ void __launch_bounds__(256)
mma_gemm(const __nv_bfloat16* __restrict__ Ah, const __nv_bfloat16* __restrict__ Al,
         const __nv_bfloat16* __restrict__ Bh, const __nv_bfloat16* __restrict__ Bl,
         const float* __restrict__ bias,
         float* __restrict__ Cf,
         __nv_bfloat16* __restrict__ ChH, __nv_bfloat16* __restrict__ ChL,
         int M, int N, int K, long strideBe, int strideBiasE)
{
    extern __shared__ char smem[];
    const uint32_t sb = smem_u32(smem);

    int tid  = threadIdx.x;
    int wid  = tid >> 5, lane = tid & 31;
    int mBase = blockIdx.y * 128;
    int nBase = blockIdx.x * 128;

    int count = M, off = 0;
    const int* lst = 0;
    if (MODE != 0) {
        int e = blockIdx.z;
        count = g_count[e];
        if (mBase >= count) return;
        off  = g_off[e];
        Bh  += (long)e * strideBe;
        Bl  += (long)e * strideBe;
        bias += (long)e * strideBiasE;
        lst  = g_list + off;
    }

    if (tid < 128) *(float*)(smem + SM_BIAS + tid * 4) = bias[nBase + tid];

    // ---- cp.async source setup: thread -> (row r, 32B half hf)
    int r  = tid >> 1;
    int hf = tid & 1;
    long aRow;
    {
        int mIdxL = mBase + r;
        if (MODE == 0)      aRow = mIdxL;
        else if (MODE == 1) aRow = (long)(lst[min(mIdxL, count - 1)] >> 1);
        else                aRow = (long)off + min(mIdxL, count - 1);
    }
    const char* aH = (const char*)(Ah + aRow * (long)K) + hf * 32;
    const char* aL = (const char*)(Al + aRow * (long)K) + hf * 32;
    const char* bH = (const char*)(Bh + (long)(nBase + r) * K) + hf * 32;
    const char* bL = (const char*)(Bl + (long)(nBase + r) * K) + hf * 32;
    uint32_t d0 = sb + (uint32_t)(r * TSB + hf * 32);

    const int NC = K >> 5;   // 32-K chunks

    // prologue: stage chunk 0 into buffer 0
    {
        CP16(d0,               aH);      CP16(d0 + 16,               aH + 16);
        CP16(d0 + PL,          aL);      CP16(d0 + PL + 16,          aL + 16);
        CP16(d0 + 2 * PL,      bH);      CP16(d0 + 2 * PL + 16,      bH + 16);
        CP16(d0 + 3 * PL,      bL);      CP16(d0 + 3 * PL + 16,      bL + 16);
        CPCOMMIT();
    }

    // warp compute setup
    int wm = wid >> 2;           // 0..1  (m half)
    int wn = wid & 3;            // 0..3  (n quarter)
    uint32_t laneoff = (uint32_t)((lane & 15) * TSB + (lane >> 4) * 16);
    uint32_t aBaseOff = (uint32_t)(wm * 64 * TSB) + laneoff;
    uint32_t bBaseOff = (uint32_t)(2 * PL + wn * 32 * TSB) + laneoff;

    float acc[4][4][4];
    #pragma unroll
    for (int i = 0; i < 4; i++)
        #pragma unroll
        for (int j = 0; j < 4; j++)
            #pragma unroll
            for (int q = 0; q < 4; q++) acc[i][j][q] = 0.f;

    for (int c = 0; c < NC; c++) {
        if (c + 1 < NC) {
            long ob = (long)(c + 1) * 64;     // 32 bf16 = 64 bytes
            uint32_t db = d0 + ((c + 1) & 1) * BUFB;
            CP16(db,              aH + ob);      CP16(db + 16,              aH + ob + 16);
            CP16(db + PL,         aL + ob);      CP16(db + PL + 16,         aL + ob + 16);
            CP16(db + 2 * PL,     bH + ob);      CP16(db + 2 * PL + 16,     bH + ob + 16);
            CP16(db + 3 * PL,     bL + ob);      CP16(db + 3 * PL + 16,     bL + ob + 16);
            CPCOMMIT();
            CPWAIT1();
        } else {
            CPWAIT0();
        }
        __syncthreads();

        uint32_t base = sb + (c & 1) * BUFB;
        #pragma unroll
        for (int ks = 0; ks < 2; ks++) {
            uint32_t ah[4][4], al[4][4], bh[2][4], bl[2][4];
            #pragma unroll
            for (int mi = 0; mi < 4; mi++) {
                uint32_t ad = base + aBaseOff + mi * (16 * TSB) + ks * 32;
                LDSM4(ah[mi], ad);
                LDSM4(al[mi], ad + PL);
            }
            #pragma unroll
            for (int np = 0; np < 2; np++) {
                uint32_t bd = base + bBaseOff + np * (16 * TSB) + ks * 32;
                LDSM4(bh[np], bd);
                LDSM4(bl[np], bd + PL);
            }
            // pass 0: hi*hi, pass 1: hi*lo, pass 2: lo*hi — interleaved so the
            // 3 dependent MMAs on each accumulator are 16 instructions apart
            #pragma unroll
            for (int mi = 0; mi < 4; mi++)
                #pragma unroll
                for (int nj = 0; nj < 4; nj++) {
                    int np = nj >> 1, s = nj & 1;
                    mma16816(acc[mi][nj], ah[mi], bh[np][s], bh[np][s + 2]);
                }
            #pragma unroll
            for (int mi = 0; mi < 4; mi++)
                #pragma unroll
                for (int nj = 0; nj < 4; nj++) {
                    int np = nj >> 1, s = nj & 1;
                    mma16816(acc[mi][nj], ah[mi], bl[np][s], bl[np][s + 2]);
                }
            #pragma unroll
            for (int mi = 0; mi < 4; mi++)
                #pragma unroll
                for (int nj = 0; nj < 4; nj++) {
                    int np = nj >> 1, s = nj & 1;
                    mma16816(acc[mi][nj], al[mi], bh[np][s], bh[np][s + 2]);
                }
        }
        __syncthreads();
    }

    // ---- epilogue
    int g  = lane >> 2;
    int tg = lane & 3;
    const float* sbias = (const float*)(smem + SM_BIAS);

    #pragma unroll
    for (int mi = 0; mi < 4; mi++) {
        #pragma unroll
        for (int hrow = 0; hrow < 2; hrow++) {
            int rm = wm * 64 + mi * 16 + g + hrow * 8;  // row in tile
            int m  = mBase + rm;
            if (MODE != 0 && m >= count) continue;
            long cRow; float scl = 1.f;
            if (MODE == 0)      cRow = m;
            else if (MODE == 1) cRow = (long)off + m;
            else { int slot = lst[m]; cRow = slot; scl = g_tprob[slot]; }
            #pragma unroll
            for (int nj = 0; nj < 4; nj++) {
                int col = wn * 32 + nj * 8 + tg * 2;
                float vx = acc[mi][nj][hrow * 2]     + sbias[col];
                float vy = acc[mi][nj][hrow * 2 + 1] + sbias[col + 1];
                if (MODE == 1) {
                    vx = gelu_f(vx); vy = gelu_f(vy);
                    __nv_bfloat16 hx = __float2bfloat16_rn(vx);
                    __nv_bfloat16 hy = __float2bfloat16_rn(vy);
                    __nv_bfloat162 H; H.x = hx; H.y = hy;
                    __nv_bfloat162 L;
                    L.x = __float2bfloat16_rn(vx - __bfloat162float(hx));
                    L.y = __float2bfloat16_rn(vy - __bfloat162float(hy));
                    long idx = cRow * (long)N + nBase + col;
                    *(__nv_bfloat162*)(ChH + idx) = H;
                    *(__nv_bfloat162*)(ChL + idx) = L;
                } else {
                    float2 v; v.x = vx * scl; v.y = vy * scl;
                    *(float2*)(Cf + cRow * (long)N + nBase + col) = v;
                }
            }
        }
    }
}

// ---------------- flash attention (fp32, 64q x 64k tiles, HD=64) -------------
// epilogue writes hi/lo bf16 planes (consumed by out-proj GEMM)
__global__ void __launch_bounds__(256) attn_kernel(
    const float* __restrict__ qkv,
    __nv_bfloat16* __restrict__ outH, __nv_bfloat16* __restrict__ outL)
{
    extern __shared__ float sm[];
    const int LD = 65;
    float* Qs = sm;
    float* Ks = sm + 64 * LD;
    float* Vs = sm + 2 * 64 * LD;
    float* Ps = sm + 3 * 64 * LD;

    int tid = threadIdx.x;
    int bh  = blockIdx.y;
    int b   = bh >> 4, h = bh & 15;
    int q0  = blockIdx.x * 64;
    const float* qb = qkv + (long)b * SS * QKVD + h * HDIM;
    const float* kb = qb + DIM;
    const float* vb = qb + 2 * DIM;

    int lr = tid >> 2;
    int lc = (tid & 3) * 4;

    #pragma unroll
    for (int u = 0; u < 4; u++) {
        int d = lc + u * 16;
        float4 v = *(const float4*)(qb + (long)(q0 + lr) * QKVD + d);
        Qs[lr * LD + d + 0] = v.x; Qs[lr * LD + d + 1] = v.y;
        Qs[lr * LD + d + 2] = v.z; Qs[lr * LD + d + 3] = v.w;
    }

    int tx = tid & 15, ty = tid >> 4;
    float m_i[4], l_i[4], o[4][4];
    #pragma unroll
    for (int i = 0; i < 4; i++) {
        m_i[i] = -1e30f; l_i[i] = 0.f;
        #pragma unroll
        for (int j = 0; j < 4; j++) o[i][j] = 0.f;
    }

    for (int kt = 0; kt < SS; kt += 64) {
        __syncthreads();
        #pragma unroll
        for (int u = 0; u < 4; u++) {
            int d = lc + u * 16;
            float4 kv = *(const float4*)(kb + (long)(kt + lr) * QKVD + d);
            float4 vv = *(const float4*)(vb + (long)(kt + lr) * QKVD + d);
            Ks[lr * LD + d + 0] = kv.x; Ks[lr * LD + d + 1] = kv.y;
            Ks[lr * LD + d + 2] = kv.z; Ks[lr * LD + d + 3] = kv.w;
            Vs[lr * LD + d + 0] = vv.x; Vs[lr * LD + d + 1] = vv.y;
            Vs[lr * LD + d + 2] = vv.z; Vs[lr * LD + d + 3] = vv.w;
        }
        __syncthreads();

        float s[4][4];
        #pragma unroll
        for (int i = 0; i < 4; i++)
            #pragma unroll
            for (int j = 0; j < 4; j++) s[i][j] = 0.f;
        #pragma unroll 8
        for (int d = 0; d < 64; d++) {
            float a[4], bq[4];
            #pragma unroll
            for (int i = 0; i < 4; i++) a[i]  = Qs[(ty * 4 + i) * LD + d];
            #pragma unroll
            for (int j = 0; j < 4; j++) bq[j] = Ks[(tx * 4 + j) * LD + d];
            #pragma unroll
            for (int i = 0; i < 4; i++)
                #pragma unroll
                for (int j = 0; j < 4; j++) s[i][j] += a[i] * bq[j];
        }

        #pragma unroll
        for (int i = 0; i < 4; i++) {
            float rm = -1e30f;
            #pragma unroll
            for (int j = 0; j < 4; j++) { s[i][j] *= 0.125f; rm = fmaxf(rm, s[i][j]); }
            #pragma unroll
            for (int o2 = 8; o2 >= 1; o2 >>= 1)
                rm = fmaxf(rm, __shfl_xor_sync(0xffffffffu, rm, o2));
            float mn    = fmaxf(m_i[i], rm);
            float alpha = expf(m_i[i] - mn);
            m_i[i] = mn;
            float rs = 0.f;
            #pragma unroll
            for (int j = 0; j < 4; j++) { s[i][j] = expf(s[i][j] - mn); rs += s[i][j]; }
            #pragma unroll
            for (int o2 = 8; o2 >= 1; o2 >>= 1)
                rs += __shfl_xor_sync(0xffffffffu, rs, o2);
            l_i[i] = l_i[i] * alpha + rs;
            #pragma unroll
            for (int j = 0; j < 4; j++) {
                o[i][j] *= alpha;
                Ps[(ty * 4 + i) * LD + tx * 4 + j] = s[i][j];
            }
        }
        __syncthreads();

        #pragma unroll 8
        for (int c = 0; c < 64; c++) {
            float a[4], bv[4];
            #pragma unroll
            for (int i = 0; i < 4; i++) a[i]  = Ps[(ty * 4 + i) * LD + c];
            #pragma unroll
            for (int j = 0; j < 4; j++) bv[j] = Vs[c * LD + tx * 4 + j];
            #pragma unroll
            for (int i = 0; i < 4; i++)
                #pragma unroll
                for (int j = 0; j < 4; j++) o[i][j] += a[i] * bv[j];
        }
    }

    #pragma unroll
    for (int i = 0; i < 4; i++) {
        float inv = 1.f / l_i[i];
        long row  = (long)b * SS + q0 + ty * 4 + i;
        #pragma unroll
        for (int j = 0; j < 4; j++) {
            float v = o[i][j] * inv;
            long idx = row * DIM + h * HDIM + tx * 4 + j;
            __nv_bfloat16 hb = __float2bfloat16_rn(v);
            outH[idx] = hb;
            outL[idx] = __float2bfloat16_rn(v - __bfloat162float(hb));
        }
    }
}

// ---------------- residual + LayerNorm; also emits x1 hi/lo planes ----------
__global__ void __launch_bounds__(256) ln_res_kernel(
    const float* __restrict__ a, const float* __restrict__ b,
    const float* __restrict__ g, const float* __restrict__ bt,
    float* __restrict__ out,
    __nv_bfloat16* __restrict__ outH, __nv_bfloat16* __restrict__ outL)
{
    long t  = blockIdx.x;
    int tid = threadIdx.x;
    float4 va = ((const float4*)(a + t * DIM))[tid];
    float4 vb = ((const float4*)(b + t * DIM))[tid];
    float v[4] = { va.x + vb.x, va.y + vb.y, va.z + vb.z, va.w + vb.w };
    float s1 = v[0] + v[1] + v[2] + v[3];
    float s2 = v[0]*v[0] + v[1]*v[1] + v[2]*v[2] + v[3]*v[3];
    #pragma unroll
    for (int o2 = 16; o2 >= 1; o2 >>= 1) {
        s1 += __shfl_xor_sync(0xffffffffu, s1, o2);
        s2 += __shfl_xor_sync(0xffffffffu, s2, o2);
    }
    __shared__ float r1[8], r2[8], mv[2];
    if ((tid & 31) == 0) { r1[tid >> 5] = s1; r2[tid >> 5] = s2; }
    __syncthreads();
    if (tid == 0) {
        float A = 0.f, Bq = 0.f;
        #pragma unroll
        for (int w = 0; w < 8; w++) { A += r1[w]; Bq += r2[w]; }
        float mean = A * (1.f / DIM);
        float var  = Bq * (1.f / DIM) - mean * mean;
        mv[0] = mean; mv[1] = rsqrtf(var + 1e-5f);
    }
    __syncthreads();
    float mean = mv[0], rstd = mv[1];
    float4 gg  = ((const float4*)g)[tid];
    float4 bbv = ((const float4*)bt)[tid];
    float4 ov;
    ov.x = (v[0] - mean) * rstd * gg.x + bbv.x;
    ov.y = (v[1] - mean) * rstd * gg.y + bbv.y;
    ov.z = (v[2] - mean) * rstd * gg.z + bbv.z;
    ov.w = (v[3] - mean) * rstd * gg.w + bbv.w;
    ((float4*)(out + t * DIM))[tid] = ov;

    __nv_bfloat16 h0 = __float2bfloat16_rn(ov.x), h1 = __float2bfloat16_rn(ov.y);
    __nv_bfloat16 h2 = __float2bfloat16_rn(ov.z), h3 = __float2bfloat16_rn(ov.w);
    __nv_bfloat162 H0; H0.x = h0; H0.y = h1;
    __nv_bfloat162 H1; H1.x = h2; H1.y = h3;
    __nv_bfloat162 L0, L1;
    L0.x = __float2bfloat16_rn(ov.x - __bfloat162float(h0));
    L0.y = __float2bfloat16_rn(ov.y - __bfloat162float(h1));
    L1.x = __float2bfloat16_rn(ov.z - __bfloat162float(h2));
    L1.y = __float2bfloat16_rn(ov.w - __bfloat162float(h3));
    ((__nv_bfloat162*)(outH + t * DIM))[2 * tid]     = H0;
    ((__nv_bfloat162*)(outH + t * DIM))[2 * tid + 1] = H1;
    ((__nv_bfloat162*)(outL + t * DIM))[2 * tid]     = L0;
    ((__nv_bfloat162*)(outL + t * DIM))[2 * tid + 1] = L1;
}

// ---------------- combine MoE slots + residual + LN2 -> d_out ----------------
__global__ void __launch_bounds__(256) ln2_kernel(
    const float* __restrict__ x1, const float* __restrict__ moe2,
    const float* __restrict__ g, const float* __restrict__ bt,
    float* __restrict__ out)
{
    long t  = blockIdx.x;
    int tid = threadIdx.x;
    float4 va = ((const float4*)(x1   + t * DIM))[tid];
    float4 vb = ((const float4*)(moe2 + (2 * t)     * DIM))[tid];
    float4 vc = ((const float4*)(moe2 + (2 * t + 1) * DIM))[tid];
    float v[4] = { va.x + vb.x + vc.x, va.y + vb.y + vc.y,
                   va.z + vb.z + vc.z, va.w + vb.w + vc.w };
    float s1 = v[0] + v[1] + v[2] + v[3];
    float s2 = v[0]*v[0] + v[1]*v[1] + v[2]*v[2] + v[3]*v[3];
    #pragma unroll
    for (int o2 = 16; o2 >= 1; o2 >>= 1) {
        s1 += __shfl_xor_sync(0xffffffffu, s1, o2);
        s2 += __shfl_xor_sync(0xffffffffu, s2, o2);
    }
    __shared__ float r1[8], r2[8], mv[2];
    if ((tid & 31) == 0) { r1[tid >> 5] = s1; r2[tid >> 5] = s2; }
    __syncthreads();
    if (tid == 0) {
        float A = 0.f, Bq = 0.f;
        #pragma unroll
        for (int w = 0; w < 8; w++) { A += r1[w]; Bq += r2[w]; }
        float mean = A * (1.f / DIM);
        float var  = Bq * (1.f / DIM) - mean * mean;
        mv[0] = mean; mv[1] = rsqrtf(var + 1e-5f);
    }
    __syncthreads();
    float mean = mv[0], rstd = mv[1];
    float4 gg  = ((const float4*)g)[tid];
    float4 bbv = ((const float4*)bt)[tid];
    float4 ov;
    ov.x = (v[0] - mean) * rstd * gg.x + bbv.x;
    ov.y = (v[1] - mean) * rstd * gg.y + bbv.y;
    ov.z = (v[2] - mean) * rstd * gg.z + bbv.z;
    ov.w = (v[3] - mean) * rstd * gg.w + bbv.w;
    ((float4*)(out + t * DIM))[tid] = ov;
}

// ---------------- gate: logits, softmax usage, top-2 -------------------------
__global__ void __launch_bounds__(256) gate_kernel(
    const float* __restrict__ x, const float* __restrict__ gw,
    const float* __restrict__ gb)
{
    int t = blockIdx.x;
    int w = threadIdx.x >> 5, lane = threadIdx.x & 31;
    const float* xr = x + (long)t * DIM;
    const float* wr = gw + w * DIM;
    float s = 0.f;
    for (int d = lane; d < DIM; d += 32) s += xr[d] * wr[d];
    #pragma unroll
    for (int o2 = 16; o2 >= 1; o2 >>= 1) s += __shfl_xor_sync(0xffffffffu, s, o2);
    __shared__ float lg[NEXP];
    if (lane == 0) lg[w] = s + gb[w];
    __syncthreads();
    if (threadIdx.x == 0) {
        float mx = lg[0];
        #pragma unroll
        for (int e = 1; e < NEXP; e++) mx = fmaxf(mx, lg[e]);
        float ex[NEXP], sum = 0.f;
        #pragma unroll
        for (int e = 0; e < NEXP; e++) { ex[e] = expf(lg[e] - mx); sum += ex[e]; }
        float inv = 1.f / sum;
        #pragma unroll
        for (int e = 0; e < NEXP; e++) atomicAdd(&g_usage[e], ex[e] * inv);
        int e0 = 0;
        #pragma unroll
        for (int e = 1; e < NEXP; e++) if (lg[e] > lg[e0]) e0 = e;
        int e1 = -1;
        #pragma unroll
        for (int e = 0; e < NEXP; e++)
            if (e != e0 && (e1 < 0 || lg[e] > lg[e1])) e1 = e;
        float z  = expf(lg[e1] - lg[e0]);
        float p0 = 1.f / (1.f + z);
        g_tidx[2 * t]     = e0;  g_tidx[2 * t + 1]  = e1;
        g_tprob[2 * t]    = p0;  g_tprob[2 * t + 1] = z * p0;
        atomicAdd(&g_count[e0], 1);
        atomicAdd(&g_count[e1], 1);
    }
}

__global__ void k_offsets() {
    if (threadIdx.x == 0) {
        int a = 0;
        for (int e = 0; e < NEXP; e++) { g_off[e] = a; a += g_count[e]; }
    }
}

__global__ void k_fill() {
    int t = blockIdx.x * blockDim.x + threadIdx.x;
    if (t < TOK) {
        #pragma unroll
        for (int k = 0; k < 2; k++) {
            int e   = g_tidx[2 * t + k];
            int pos = atomicAdd(&g_fill[e], 1);
            g_list[g_off[e] + pos] = 2 * t + k;
        }
    }
}

__global__ void k_aux(float* out) {
    float s = 0.f;
    #pragma unroll
    for (int e = 0; e < NEXP; e++) {
        float u = g_usage[e] * (1.f / TOK);
        s += u * u;
    }
    out[(size_t)TOK * DIM] = (float)NEXP * s;
}

// ---------------- launch ----------------
extern "C" void kernel_launch(void* const* d_in, const int* in_sizes, int n_in,
                              void* d_out, int out_size)
{
    (void)in_sizes; (void)n_in;
    const float* src  = (const float*)d_in[0];
    const float* ipw  = (const float*)d_in[1];
    const float* ipb  = (const float*)d_in[2];
    const float* outw = (const float*)d_in[3];
    const float* outb = (const float*)d_in[4];
    const float* gw   = (const float*)d_in[5];
    const float* gb   = (const float*)d_in[6];
    const float* w1   = (const float*)d_in[7];
    const float* b1   = (const float*)d_in[8];
    const float* w2   = (const float*)d_in[9];
    const float* b2   = (const float*)d_in[10];
    const float* ln1g = (const float*)d_in[11];
    const float* ln1b = (const float*)d_in[12];
    const float* ln2g = (const float*)d_in[13];
    const float* ln2b = (const float*)d_in[14];
    float* out = (float*)d_out;

    float *p_qkv, *p_proj, *p_x1, *p_moe2;
    cudaGetSymbolAddress((void**)&p_qkv,  g_qkv);
    cudaGetSymbolAddress((void**)&p_proj, g_proj);
    cudaGetSymbolAddress((void**)&p_x1,   g_x1);
    cudaGetSymbolAddress((void**)&p_moe2, g_moe2);
    __nv_bfloat16 *srcH, *srcL, *attnH, *attnL, *x1H, *x1L, *hH, *hL;
    __nv_bfloat16 *ipwH, *ipwL, *outwH, *outwL, *w1H, *w1L, *w2H, *w2L;
    cudaGetSymbolAddress((void**)&srcH,  g_srcH);
    cudaGetSymbolAddress((void**)&srcL,  g_srcL);
    cudaGetSymbolAddress((void**)&attnH, g_attnH);
    cudaGetSymbolAddress((void**)&attnL, g_attnL);
    cudaGetSymbolAddress((void**)&x1H,   g_x1H);
    cudaGetSymbolAddress((void**)&x1L,   g_x1L);
    cudaGetSymbolAddress((void**)&hH,    g_hH);
    cudaGetSymbolAddress((void**)&hL,    g_hL);
    cudaGetSymbolAddress((void**)&ipwH,  g_ipwH);
    cudaGetSymbolAddress((void**)&ipwL,  g_ipwL);
    cudaGetSymbolAddress((void**)&outwH, g_outwH);
    cudaGetSymbolAddress((void**)&outwL, g_outwL);
    cudaGetSymbolAddress((void**)&w1H,   g_w1H);
    cudaGetSymbolAddress((void**)&w1L,   g_w1L);
    cudaGetSymbolAddress((void**)&w2H,   g_w2H);
    cudaGetSymbolAddress((void**)&w2L,   g_w2L);

    const int ATTN_SMEM = 4 * 64 * 65 * (int)sizeof(float);
    cudaFuncSetAttribute(attn_kernel,
                         cudaFuncAttributeMaxDynamicSharedMemorySize, ATTN_SMEM);
    cudaFuncSetAttribute(mma_gemm<0>,
                         cudaFuncAttributeMaxDynamicSharedMemorySize, SM_TOTAL);
    cudaFuncSetAttribute(mma_gemm<1>,
                         cudaFuncAttributeMaxDynamicSharedMemorySize, SM_TOTAL);
    cudaFuncSetAttribute(mma_gemm<2>,
                         cudaFuncAttributeMaxDynamicSharedMemorySize, SM_TOTAL);

    // 0) per-replay init + operand plane preparation
    k_init<<<1, 32>>>();
    {
        long n;
        n = (long)TOK * DIM / 4;
        k_conv<<<(int)((n + 255) / 256), 256>>>(src, srcH, srcL, n);
        n = (long)QKVD * DIM / 4;
        k_conv<<<(int)((n + 255) / 256), 256>>>(ipw, ipwH, ipwL, n);
        n = (long)DIM * DIM / 4;
        k_conv<<<(int)((n + 255) / 256), 256>>>(outw, outwH, outwL, n);
        n = (long)NEXP * FDIM * DIM / 4;
        k_conv<<<(int)((n + 255) / 256), 256>>>(w1, w1H, w1L, n);
        n = (long)NEXP * DIM * FDIM / 4;
        k_conv<<<(int)((n + 255) / 256), 256>>>(w2, w2H, w2L, n);
    }

    // 1) QKV projection (fp32 out for attention)
    mma_gemm<0><<<dim3(QKVD / 128, TOK / 128, 1), 256, SM_TOTAL>>>(
        srcH, srcL, ipwH, ipwL, ipb, p_qkv, 0, 0, TOK, QKVD, DIM, 0, 0);

    // 2) attention -> hi/lo planes
    attn_kernel<<<dim3(SS / 64, BB * NHEAD), 256, ATTN_SMEM>>>(p_qkv, attnH, attnL);

    // 3) output projection (fp32 out for LN)
    mma_gemm<0><<<dim3(DIM / 128, TOK / 128, 1), 256, SM_TOTAL>>>(
        attnH, attnL, outwH, outwL, outb, p_proj, 0, 0, TOK, DIM, DIM, 0, 0);

    // 4) x1 = LN(src + attn_out); also emit x1 planes
    ln_res_kernel<<<TOK, 256>>>(p_proj, src, ln1g, ln1b, p_x1, x1H, x1L);

    // 5) gating
    gate_kernel<<<TOK, 256>>>(p_x1, gw, gb);
    k_offsets<<<1, 32>>>();
    k_fill<<<TOK / 256, 256>>>();

    // 6) expert GEMM1: h = gelu(x1 @ w1[e]^T + b1[e]) -> hi/lo planes
    mma_gemm<1><<<dim3(FDIM / 128, TOK / 128, NEXP), 256, SM_TOTAL>>>(
        x1H, x1L, w1H, w1L, b1, 0, hH, hL,
        TOK, FDIM, DIM, (long)FDIM * DIM, FDIM);

    // 7) expert GEMM2: eo = (h @ w2[e]^T + b2[e]) * prob -> fp32 scatter
    mma_gemm<2><<<dim3(DIM / 128, TOK / 128, NEXP), 256, SM_TOTAL>>>(
        hH, hL, w2H, w2L, b2, p_moe2, 0, 0,
        TOK, DIM, FDIM, (long)DIM * FDIM, DIM);

    // 8) out = LN(x1 + moe_out)
    ln2_kernel<<<TOK, 256>>>(p_x1, p_moe2, ln2g, ln2b, out);

    // 9) aux loss
    if (out_size > TOK * DIM) k_aux<<<1, 1>>>(out);
}

// round 8
// speedup vs baseline: 2.0292x; 1.1950x over previous
#include <cuda_runtime.h>
#include <cuda_bf16.h>
#include <math.h>
#include <stdint.h>

// ---------------- problem constants ----------------
#define BB    2
#define SS    1024
#define TOK   2048          // B*S
#define DIM   1024
#define QKVD  3072
#define NHEAD 16
#define HDIM  64
#define NEXP  8
#define FDIM  4096
#define NSLOT 4096          // TOK * top_k

// ---------------- device scratch (no allocs allowed) ----------------
__device__ __align__(128) float g_proj[(size_t)TOK * DIM];
__device__ __align__(128) float g_x1  [(size_t)TOK * DIM];
__device__ __align__(128) float g_moe2[(size_t)NSLOT * DIM];

// hi/lo bf16 operand planes
__device__ __align__(128) __nv_bfloat16 g_qkvH [(size_t)TOK * QKVD];
__device__ __align__(128) __nv_bfloat16 g_qkvL [(size_t)TOK * QKVD];
__device__ __align__(128) __nv_bfloat16 g_srcH [(size_t)TOK * DIM];
__device__ __align__(128) __nv_bfloat16 g_srcL [(size_t)TOK * DIM];
__device__ __align__(128) __nv_bfloat16 g_attnH[(size_t)TOK * DIM];
__device__ __align__(128) __nv_bfloat16 g_attnL[(size_t)TOK * DIM];
__device__ __align__(128) __nv_bfloat16 g_x1H  [(size_t)TOK * DIM];
__device__ __align__(128) __nv_bfloat16 g_x1L  [(size_t)TOK * DIM];
__device__ __align__(128) __nv_bfloat16 g_hH   [(size_t)NSLOT * FDIM];
__device__ __align__(128) __nv_bfloat16 g_hL   [(size_t)NSLOT * FDIM];
__device__ __align__(128) __nv_bfloat16 g_ipwH [(size_t)QKVD * DIM];
__device__ __align__(128) __nv_bfloat16 g_ipwL [(size_t)QKVD * DIM];
__device__ __align__(128) __nv_bfloat16 g_outwH[(size_t)DIM * DIM];
__device__ __align__(128) __nv_bfloat16 g_outwL[(size_t)DIM * DIM];
__device__ __align__(128) __nv_bfloat16 g_w1H  [(size_t)NEXP * FDIM * DIM];
__device__ __align__(128) __nv_bfloat16 g_w1L  [(size_t)NEXP * FDIM * DIM];
__device__ __align__(128) __nv_bfloat16 g_w2H  [(size_t)NEXP * DIM * FDIM];
__device__ __align__(128) __nv_bfloat16 g_w2L  [(size_t)NEXP * DIM * FDIM];

__device__ int   g_tidx[NSLOT];
__device__ float g_tprob[NSLOT];
__device__ float g_usage[NEXP];
__device__ int   g_count[NEXP];
__device__ int   g_off[NEXP];
__device__ int   g_fill[NEXP];
__device__ int   g_list[NSLOT];

__device__ __forceinline__ float gelu_f(float x) {
    return 0.5f * x * (1.0f + erff(x * 0.70710678118654752f));
}

// ---------------- PTX helpers (all compute_103-legal) ----------------
__device__ __forceinline__ uint32_t smem_u32(const void* p) {
    uint32_t a;
    asm("{ .reg .u64 t; cvta.to.shared.u64 t, %1; cvt.u32.u64 %0, t; }"
        : "=r"(a) : "l"(p));
    return a;
}

#define CP16(dst, src) \
    asm volatile("cp.async.cg.shared.global [%0], [%1], 16;" \
                 :: "r"(dst), "l"(src) : "memory")
#define CPCOMMIT()  asm volatile("cp.async.commit_group;" ::: "memory")
#define CPWAIT0()   asm volatile("cp.async.wait_group 0;" ::: "memory")
#define CPWAIT1()   asm volatile("cp.async.wait_group 1;" ::: "memory")

#define LDSM4(R, addr) \
    asm volatile("ldmatrix.sync.aligned.m8n8.x4.shared.b16 {%0,%1,%2,%3}, [%4];" \
        : "=r"((R)[0]), "=r"((R)[1]), "=r"((R)[2]), "=r"((R)[3]) : "r"(addr))
#define LDSM4T(R, addr) \
    asm volatile("ldmatrix.sync.aligned.m8n8.x4.trans.shared.b16 {%0,%1,%2,%3}, [%4];" \
        : "=r"((R)[0]), "=r"((R)[1]), "=r"((R)[2]), "=r"((R)[3]) : "r"(addr))

__device__ __forceinline__ void mma16816(float* c, const uint32_t* a,
                                         uint32_t b0, uint32_t b1) {
    asm volatile(
        "mma.sync.aligned.m16n8k16.row.col.f32.bf16.bf16.f32 "
        "{%0,%1,%2,%3}, {%4,%5,%6,%7}, {%8,%9}, {%0,%1,%2,%3};"
        : "+f"(c[0]), "+f"(c[1]), "+f"(c[2]), "+f"(c[3])
        : "r"(a[0]), "r"(a[1]), "r"(a[2]), "r"(a[3]), "r"(b0), "r"(b1));
}

__device__ __forceinline__ uint32_t packbf(float a, float b) {
    __nv_bfloat162 t;
    t.x = __float2bfloat16_rn(a);
    t.y = __float2bfloat16_rn(b);
    return *(uint32_t*)&t;
}

// ---------------- init (re-zero per replay) ----------------
__global__ void k_init() {
    int i = threadIdx.x;
    if (i < NEXP) { g_usage[i] = 0.f; g_count[i] = 0; g_fill[i] = 0; }
}

// ---------------- fp32 -> (hi, lo) bf16 planes ----------------
__global__ void __launch_bounds__(256) k_conv(
    const float* __restrict__ x, __nv_bfloat16* __restrict__ hi,
    __nv_bfloat16* __restrict__ lo, long n4)
{
    long i = (long)blockIdx.x * blockDim.x + threadIdx.x;
    if (i >= n4) return;
    float4 v = ((const float4*)x)[i];
    __nv_bfloat16 h0 = __float2bfloat16_rn(v.x);
    __nv_bfloat16 h1 = __float2bfloat16_rn(v.y);
    __nv_bfloat16 h2 = __float2bfloat16_rn(v.z);
    __nv_bfloat16 h3 = __float2bfloat16_rn(v.w);
    __nv_bfloat162 H0; H0.x = h0; H0.y = h1;
    __nv_bfloat162 H1; H1.x = h2; H1.y = h3;
    __nv_bfloat162 L0, L1;
    L0.x = __float2bfloat16_rn(v.x - __bfloat162float(h0));
    L0.y = __float2bfloat16_rn(v.y - __bfloat162float(h1));
    L1.x = __float2bfloat16_rn(v.z - __bfloat162float(h2));
    L1.y = __float2bfloat16_rn(v.w - __bfloat162float(h3));
    ((__nv_bfloat162*)hi)[2 * i]     = H0;
    ((__nv_bfloat162*)hi)[2 * i + 1] = H1;
    ((__nv_bfloat162*)lo)[2 * i]     = L0;
    ((__nv_bfloat162*)lo)[2 * i + 1] = L1;
}

// =====================================================================
// bf16-split NT GEMM via mma.sync: C[m,n] = sum_k A[m,k]*B[n,k]
//   tile 128x128x32, 8 warps (2m x 4n), hi/lo planes, cp.async double buffer
// MODE 0: C fp32 = acc + bias
// MODE 1: A rows gathered via g_list (token=slot>>1); gelu(acc+bias) ->
//         hi/lo bf16 planes at row g_off[e]+m
// MODE 2: A rows = g_off[e]+m; (acc+bias)*prob -> fp32 scatter to row slot
// MODE 3: plain A rows; (acc+bias) [cols<DIM scaled 1/8] -> hi/lo planes
// =====================================================================
#define TSB   80            // smem row stride bytes (64 data + 16 pad)
#define PL    10240         // one plane: 128 rows * 80B
#define BUFB  40960         // 4 planes (Ahi, Alo, Bhi, Blo)
#define SM_BIAS  81920      // after 2 buffers
#define SM_TOTAL (SM_BIAS + 512)

template<int MODE>
__global__ void __launch_bounds__(256)
mma_gemm(const __nv_bfloat16* __restrict__ Ah, const __nv_bfloat16* __restrict__ Al,
         const __nv_bfloat16* __restrict__ Bh, const __nv_bfloat16* __restrict__ Bl,
         const float* __restrict__ bias,
         float* __restrict__ Cf,
         __nv_bfloat16* __restrict__ ChH, __nv_bfloat16* __restrict__ ChL,
         int M, int N, int K, long strideBe, int strideBiasE)
{
    extern __shared__ char smem[];
    const uint32_t sb = smem_u32(smem);

    int tid  = threadIdx.x;
    int wid  = tid >> 5, lane = tid & 31;
    int mBase = blockIdx.y * 128;
    int nBase = blockIdx.x * 128;

    int count = M, off = 0;
    const int* lst = 0;
    if (MODE == 1 || MODE == 2) {
        int e = blockIdx.z;
        count = g_count[e];
        if (mBase >= count) return;
        off  = g_off[e];
        Bh  += (long)e * strideBe;
        Bl  += (long)e * strideBe;
        bias += (long)e * strideBiasE;
        lst  = g_list + off;
    }

    if (tid < 128) *(float*)(smem + SM_BIAS + tid * 4) = bias[nBase + tid];

    // ---- cp.async source setup: thread -> (row r, 32B half hf)
    int r  = tid >> 1;
    int hf = tid & 1;
    long aRow;
    {
        int mIdxL = mBase + r;
        if (MODE == 0 || MODE == 3) aRow = mIdxL;
        else if (MODE == 1) aRow = (long)(lst[min(mIdxL, count - 1)] >> 1);
        else                aRow = (long)off + min(mIdxL, count - 1);
    }
    const char* aH = (const char*)(Ah + aRow * (long)K) + hf * 32;
    const char* aL = (const char*)(Al + aRow * (long)K) + hf * 32;
    const char* bH = (const char*)(Bh + (long)(nBase + r) * K) + hf * 32;
    const char* bL = (const char*)(Bl + (long)(nBase + r) * K) + hf * 32;
    uint32_t d0 = sb + (uint32_t)(r * TSB + hf * 32);

    const int NC = K >> 5;   // 32-K chunks

    // prologue: stage chunk 0 into buffer 0
    {
        CP16(d0,               aH);      CP16(d0 + 16,               aH + 16);
        CP16(d0 + PL,          aL);      CP16(d0 + PL + 16,          aL + 16);
        CP16(d0 + 2 * PL,      bH);      CP16(d0 + 2 * PL + 16,      bH + 16);
        CP16(d0 + 3 * PL,      bL);      CP16(d0 + 3 * PL + 16,      bL + 16);
        CPCOMMIT();
    }

    // warp compute setup
    int wm = wid >> 2;           // 0..1  (m half)
    int wn = wid & 3;            // 0..3  (n quarter)
    uint32_t laneoff = (uint32_t)((lane & 15) * TSB + (lane >> 4) * 16);
    uint32_t aBaseOff = (uint32_t)(wm * 64 * TSB) + laneoff;
    uint32_t bBaseOff = (uint32_t)(2 * PL + wn * 32 * TSB) + laneoff;

    float acc[4][4][4];
    #pragma unroll
    for (int i = 0; i < 4; i++)
        #pragma unroll
        for (int j = 0; j < 4; j++)
            #pragma unroll
            for (int q = 0; q < 4; q++) acc[i][j][q] = 0.f;

    for (int c = 0; c < NC; c++) {
        if (c + 1 < NC) {
            long ob = (long)(c + 1) * 64;     // 32 bf16 = 64 bytes
            uint32_t db = d0 + ((c + 1) & 1) * BUFB;
            CP16(db,              aH + ob);      CP16(db + 16,              aH + ob + 16);
            CP16(db + PL,         aL + ob);      CP16(db + PL + 16,         aL + ob + 16);
            CP16(db + 2 * PL,     bH + ob);      CP16(db + 2 * PL + 16,     bH + ob + 16);
            CP16(db + 3 * PL,     bL + ob);      CP16(db + 3 * PL + 16,     bL + ob + 16);
            CPCOMMIT();
            CPWAIT1();
        } else {
            CPWAIT0();
        }
        __syncthreads();

        uint32_t base = sb + (c & 1) * BUFB;
        #pragma unroll
        for (int ks = 0; ks < 2; ks++) {
            uint32_t ah[4][4], al[4][4], bh[2][4], bl[2][4];
            #pragma unroll
            for (int mi = 0; mi < 4; mi++) {
                uint32_t ad = base + aBaseOff + mi * (16 * TSB) + ks * 32;
                LDSM4(ah[mi], ad);
                LDSM4(al[mi], ad + PL);
            }
            #pragma unroll
            for (int np = 0; np < 2; np++) {
                uint32_t bd = base + bBaseOff + np * (16 * TSB) + ks * 32;
                LDSM4(bh[np], bd);
                LDSM4(bl[np], bd + PL);
            }
            #pragma unroll
            for (int mi = 0; mi < 4; mi++)
                #pragma unroll
                for (int nj = 0; nj < 4; nj++) {
                    int np = nj >> 1, s = nj & 1;
                    mma16816(acc[mi][nj], ah[mi], bh[np][s], bh[np][s + 2]);
                }
            #pragma unroll
            for (int mi = 0; mi < 4; mi++)
                #pragma unroll
                for (int nj = 0; nj < 4; nj++) {
                    int np = nj >> 1, s = nj & 1;
                    mma16816(acc[mi][nj], ah[mi], bl[np][s], bl[np][s + 2]);
                }
            #pragma unroll
            for (int mi = 0; mi < 4; mi++)
                #pragma unroll
                for (int nj = 0; nj < 4; nj++) {
                    int np = nj >> 1, s = nj & 1;
                    mma16816(acc[mi][nj], al[mi], bh[np][s], bh[np][s + 2]);
                }
        }
        __syncthreads();
    }

    // ---- epilogue
    int g  = lane >> 2;
    int tg = lane & 3;
    const float* sbias = (const float*)(smem + SM_BIAS);
    float qs = 1.f;
    if (MODE == 3) qs = (nBase < DIM) ? 0.125f : 1.f;   // pre-scale Q by 1/sqrt(HD)

    #pragma unroll
    for (int mi = 0; mi < 4; mi++) {
        #pragma unroll
        for (int hrow = 0; hrow < 2; hrow++) {
            int rm = wm * 64 + mi * 16 + g + hrow * 8;  // row in tile
            int m  = mBase + rm;
            if ((MODE == 1 || MODE == 2) && m >= count) continue;
            long cRow; float scl = 1.f;
            if (MODE == 0 || MODE == 3) cRow = m;
            else if (MODE == 1)         cRow = (long)off + m;
            else { int slot = lst[m]; cRow = slot; scl = g_tprob[slot]; }
            #pragma unroll
            for (int nj = 0; nj < 4; nj++) {
                int col = wn * 32 + nj * 8 + tg * 2;
                float vx = acc[mi][nj][hrow * 2]     + sbias[col];
                float vy = acc[mi][nj][hrow * 2 + 1] + sbias[col + 1];
                if (MODE == 1) { vx = gelu_f(vx); vy = gelu_f(vy); }
                if (MODE == 3) { vx *= qs; vy *= qs; }
                if (MODE == 1 || MODE == 3) {
                    __nv_bfloat16 hx = __float2bfloat16_rn(vx);
                    __nv_bfloat16 hy = __float2bfloat16_rn(vy);
                    __nv_bfloat162 H; H.x = hx; H.y = hy;
                    __nv_bfloat162 L;
                    L.x = __float2bfloat16_rn(vx - __bfloat162float(hx));
                    L.y = __float2bfloat16_rn(vy - __bfloat162float(hy));
                    long idx = cRow * (long)N + nBase + col;
                    *(__nv_bfloat162*)(ChH + idx) = H;
                    *(__nv_bfloat162*)(ChL + idx) = L;
                } else {
                    float2 v; v.x = vx * scl; v.y = vy * scl;
                    *(float2*)(Cf + cRow * (long)N + nBase + col) = v;
                }
            }
        }
    }
}

// =====================================================================
// FA2-style mma attention: 128 q-rows/CTA, 8 warps x m16, K-tile 64.
// scores = (Qh + Ql) . Kh   (Q pre-scaled 1/8 in QKV epilogue)
// O      = (Ph + Pl) . Vh   (P packed reg->reg from score frags)
// Output: hi/lo bf16 planes [tok][DIM].
// =====================================================================
#define AT_STRIDE 144                    // 64 bf16 cols + 16B pad
#define AT_KVB    18432                  // Kh(9216) + Vh(9216) per buffer
#define AT_KH(b)  ((b) * AT_KVB)
#define AT_VH(b)  ((b) * AT_KVB + 9216)
#define AT_QH     36864
#define AT_QL     55296
#define AT_SMEM   73728

__global__ void __launch_bounds__(256) attn_mma(
    const __nv_bfloat16* __restrict__ qkvH,
    const __nv_bfloat16* __restrict__ qkvL,
    __nv_bfloat16* __restrict__ outH, __nv_bfloat16* __restrict__ outL)
{
    extern __shared__ char smem[];
    const uint32_t sb = smem_u32(smem);
    int tid = threadIdx.x, wid = tid >> 5, lane = tid & 31;
    int bh = blockIdx.y;
    int b  = bh >> 4, h = bh & 15;
    int q0 = blockIdx.x * 128;

    const char* Hb = (const char*)qkvH;
    const char* Lb = (const char*)qkvL;
    const long ROWB = (long)QKVD * 2;            // bytes per token row
    const long tokB = (long)b * SS;

    // ---- stage Q (both planes) + K/V tile 0 (hi plane only)
    #pragma unroll
    for (int u = 0; u < 4; u++) {
        int id = tid + u * 256;                  // 0..1023
        int row = id >> 3, ch = id & 7;
        long so = (tokB + q0 + row) * ROWB + (long)(h * 64) * 2 + ch * 16;
        CP16(sb + AT_QH + row * AT_STRIDE + ch * 16, Hb + so);
        CP16(sb + AT_QL + row * AT_STRIDE + ch * 16, Lb + so);
    }
    #pragma unroll
    for (int u = 0; u < 2; u++) {
        int id = tid + u * 256;                  // 0..511
        int row = id >> 3, ch = id & 7;
        long ko = (tokB + row) * ROWB + (long)(DIM     + h * 64) * 2 + ch * 16;
        long vo = (tokB + row) * ROWB + (long)(2 * DIM + h * 64) * 2 + ch * 16;
        CP16(sb + AT_KH(0) + row * AT_STRIDE + ch * 16, Hb + ko);
        CP16(sb + AT_VH(0) + row * AT_STRIDE + ch * 16, Hb + vo);
    }
    CPCOMMIT();
    CPWAIT0();
    __syncthreads();

    // ---- load Q fragments once (warp owns rows wid*16 .. +15)
    uint32_t qh[4][4], ql[4][4];
    {
        uint32_t rb = (uint32_t)((wid * 16 + (lane & 15)) * AT_STRIDE + (lane >> 4) * 16);
        #pragma unroll
        for (int ks = 0; ks < 4; ks++) {
            LDSM4(qh[ks], sb + AT_QH + rb + ks * 32);
            LDSM4(ql[ks], sb + AT_QL + rb + ks * 32);
        }
    }

    float m0 = -1e30f, m1 = -1e30f, l0 = 0.f, l1 = 0.f;
    float O[8][4];
    #pragma unroll
    for (int j = 0; j < 8; j++)
        #pragma unroll
        for (int q = 0; q < 4; q++) O[j][q] = 0.f;

    const int NT = SS / 64;   // 16 K-tiles
    for (int c = 0; c < NT; c++) {
        if (c + 1 < NT) {
            #pragma unroll
            for (int u = 0; u < 2; u++) {
                int id = tid + u * 256;
                int row = id >> 3, ch = id & 7;
                long ko = (tokB + (c + 1) * 64 + row) * ROWB + (long)(DIM     + h * 64) * 2 + ch * 16;
                long vo = (tokB + (c + 1) * 64 + row) * ROWB + (long)(2 * DIM + h * 64) * 2 + ch * 16;
                CP16(sb + AT_KH((c + 1) & 1) + row * AT_STRIDE + ch * 16, Hb + ko);
                CP16(sb + AT_VH((c + 1) & 1) + row * AT_STRIDE + ch * 16, Hb + vo);
            }
            CPCOMMIT();
            CPWAIT1();
        } else {
            CPWAIT0();
        }
        __syncthreads();

        // ---- scores S[m16][kk64] = Q . K^T
        float s[8][4];
        #pragma unroll
        for (int j = 0; j < 8; j++)
            #pragma unroll
            for (int q = 0; q < 4; q++) s[j][q] = 0.f;

        uint32_t kb = sb + AT_KH(c & 1) + (uint32_t)((lane & 15) * AT_STRIDE + (lane >> 4) * 16);
        #pragma unroll
        for (int ks = 0; ks < 4; ks++) {        // d chunks of 16
            uint32_t kf[4][4];
            #pragma unroll
            for (int np = 0; np < 4; np++)
                LDSM4(kf[np], kb + np * (16 * AT_STRIDE) + ks * 32);
            #pragma unroll
            for (int np = 0; np < 4; np++) {
                mma16816(s[2 * np],     qh[ks], kf[np][0], kf[np][2]);
                mma16816(s[2 * np + 1], qh[ks], kf[np][1], kf[np][3]);
            }
            #pragma unroll
            for (int np = 0; np < 4; np++) {
                mma16816(s[2 * np],     ql[ks], kf[np][0], kf[np][2]);
                mma16816(s[2 * np + 1], ql[ks], kf[np][1], kf[np][3]);
            }
        }

        // ---- online softmax (2 rows/thread; quad = lanes sharing a row)
        float rm0 = -1e30f, rm1 = -1e30f;
        #pragma unroll
        for (int j = 0; j < 8; j++) {
            rm0 = fmaxf(rm0, fmaxf(s[j][0], s[j][1]));
            rm1 = fmaxf(rm1, fmaxf(s[j][2], s[j][3]));
        }
        rm0 = fmaxf(rm0, __shfl_xor_sync(0xffffffffu, rm0, 1));
        rm0 = fmaxf(rm0, __shfl_xor_sync(0xffffffffu, rm0, 2));
        rm1 = fmaxf(rm1, __shfl_xor_sync(0xffffffffu, rm1, 1));
        rm1 = fmaxf(rm1, __shfl_xor_sync(0xffffffffu, rm1, 2));
        float mn0 = fmaxf(m0, rm0), mn1 = fmaxf(m1, rm1);
        float a0 = __expf(m0 - mn0), a1 = __expf(m1 - mn1);
        m0 = mn0; m1 = mn1;
        float rs0 = 0.f, rs1 = 0.f;
        #pragma unroll
        for (int j = 0; j < 8; j++) {
            s[j][0] = __expf(s[j][0] - mn0);
            s[j][1] = __expf(s[j][1] - mn0);
            s[j][2] = __expf(s[j][2] - mn1);
            s[j][3] = __expf(s[j][3] - mn1);
            rs0 += s[j][0] + s[j][1];
            rs1 += s[j][2] + s[j][3];
        }
        rs0 += __shfl_xor_sync(0xffffffffu, rs0, 1);
        rs0 += __shfl_xor_sync(0xffffffffu, rs0, 2);
        rs1 += __shfl_xor_sync(0xffffffffu, rs1, 1);
        rs1 += __shfl_xor_sync(0xffffffffu, rs1, 2);
        l0 = l0 * a0 + rs0;
        l1 = l1 * a1 + rs1;
        #pragma unroll
        for (int j = 0; j < 8; j++) {
            O[j][0] *= a0; O[j][1] *= a0;
            O[j][2] *= a1; O[j][3] *= a1;
        }

        // ---- pack P hi/lo as A-fragments directly from score frags
        uint32_t ph[4][4], pl[4][4];
        #pragma unroll
        for (int ks = 0; ks < 4; ks++) {
            int j0 = 2 * ks, j1 = 2 * ks + 1;
            #pragma unroll
            for (int half = 0; half < 2; half++) {
                int jj = half ? j1 : j0;
                float x = s[jj][0], y = s[jj][1], z = s[jj][2], w = s[jj][3];
                __nv_bfloat16 hx = __float2bfloat16_rn(x);
                __nv_bfloat16 hy = __float2bfloat16_rn(y);
                __nv_bfloat16 hz = __float2bfloat16_rn(z);
                __nv_bfloat16 hw = __float2bfloat16_rn(w);
                __nv_bfloat162 P0; P0.x = hx; P0.y = hy;
                __nv_bfloat162 P1; P1.x = hz; P1.y = hw;
                ph[ks][2 * half]     = *(uint32_t*)&P0;
                ph[ks][2 * half + 1] = *(uint32_t*)&P1;
                pl[ks][2 * half]     = packbf(x - __bfloat162float(hx),
                                              y - __bfloat162float(hy));
                pl[ks][2 * half + 1] = packbf(z - __bfloat162float(hz),
                                              w - __bfloat162float(hw));
            }
        }

        // ---- O += P . V  (V via ldmatrix.trans)
        uint32_t vb = sb + AT_VH(c & 1) + (uint32_t)((lane & 15) * AT_STRIDE + (lane >> 4) * 16);
        #pragma unroll
        for (int ks = 0; ks < 4; ks++) {        // kk chunks of 16
            uint32_t vf[4][4];
            #pragma unroll
            for (int np = 0; np < 4; np++)
                LDSM4T(vf[np], vb + ks * (16 * AT_STRIDE) + np * 32);
            #pragma unroll
            for (int np = 0; np < 4; np++) {
                mma16816(O[2 * np],     ph[ks], vf[np][0], vf[np][1]);
                mma16816(O[2 * np + 1], ph[ks], vf[np][2], vf[np][3]);
            }
            #pragma unroll
            for (int np = 0; np < 4; np++) {
                mma16816(O[2 * np],     pl[ks], vf[np][0], vf[np][1]);
                mma16816(O[2 * np + 1], pl[ks], vf[np][2], vf[np][3]);
            }
        }
        __syncthreads();
    }

    // ---- epilogue: O/l -> hi/lo planes at [tok][h*64 + d]
    float inv0 = 1.f / l0, inv1 = 1.f / l1;
    int g  = lane >> 2;
    int t2 = (lane & 3) * 2;
    long tok0 = (long)b * SS + q0 + wid * 16 + g;
    long tok1 = tok0 + 8;
    #pragma unroll
    for (int nj = 0; nj < 8; nj++) {
        int col = h * 64 + nj * 8 + t2;
        float v0 = O[nj][0] * inv0, v1 = O[nj][1] * inv0;
        float v2 = O[nj][2] * inv1, v3 = O[nj][3] * inv1;
        __nv_bfloat16 h0 = __float2bfloat16_rn(v0);
        __nv_bfloat16 h1 = __float2bfloat16_rn(v1);
        __nv_bfloat16 h2 = __float2bfloat16_rn(v2);
        __nv_bfloat16 h3 = __float2bfloat16_rn(v3);
        __nv_bfloat162 H0; H0.x = h0; H0.y = h1;
        __nv_bfloat162 H1; H1.x = h2; H1.y = h3;
        *(__nv_bfloat162*)(outH + tok0 * DIM + col) = H0;
        *(__nv_bfloat162*)(outH + tok1 * DIM + col) = H1;
        __nv_bfloat162 L0, L1;
        L0.x = __float2bfloat16_rn(v0 - __bfloat162float(h0));
        L0.y = __float2bfloat16_rn(v1 - __bfloat162float(h1));
        L1.x = __float2bfloat16_rn(v2 - __bfloat162float(h2));
        L1.y = __float2bfloat16_rn(v3 - __bfloat162float(h3));
        *(__nv_bfloat162*)(outL + tok0 * DIM + col) = L0;
        *(__nv_bfloat162*)(outL + tok1 * DIM + col) = L1;
    }
}

// ---------------- residual + LayerNorm; also emits x1 hi/lo planes ----------
__global__ void __launch_bounds__(256) ln_res_kernel(
    const float* __restrict__ a, const float* __restrict__ b,
    const float* __restrict__ g, const float* __restrict__ bt,
    float* __restrict__ out,
    __nv_bfloat16* __restrict__ outH, __nv_bfloat16* __restrict__ outL)
{
    long t  = blockIdx.x;
    int tid = threadIdx.x;
    float4 va = ((const float4*)(a + t * DIM))[tid];
    float4 vb = ((const float4*)(b + t * DIM))[tid];
    float v[4] = { va.x + vb.x, va.y + vb.y, va.z + vb.z, va.w + vb.w };
    float s1 = v[0] + v[1] + v[2] + v[3];
    float s2 = v[0]*v[0] + v[1]*v[1] + v[2]*v[2] + v[3]*v[3];
    #pragma unroll
    for (int o2 = 16; o2 >= 1; o2 >>= 1) {
        s1 += __shfl_xor_sync(0xffffffffu, s1, o2);
        s2 += __shfl_xor_sync(0xffffffffu, s2, o2);
    }
    __shared__ float r1[8], r2[8], mv[2];
    if ((tid & 31) == 0) { r1[tid >> 5] = s1; r2[tid >> 5] = s2; }
    __syncthreads();
    if (tid == 0) {
        float A = 0.f, Bq = 0.f;
        #pragma unroll
        for (int w = 0; w < 8; w++) { A += r1[w]; Bq += r2[w]; }
        float mean = A * (1.f / DIM);
        float var  = Bq * (1.f / DIM) - mean * mean;
        mv[0] = mean; mv[1] = rsqrtf(var + 1e-5f);
    }
    __syncthreads();
    float mean = mv[0], rstd = mv[1];
    float4 gg  = ((const float4*)g)[tid];
    float4 bbv = ((const float4*)bt)[tid];
    float4 ov;
    ov.x = (v[0] - mean) * rstd * gg.x + bbv.x;
    ov.y = (v[1] - mean) * rstd * gg.y + bbv.y;
    ov.z = (v[2] - mean) * rstd * gg.z + bbv.z;
    ov.w = (v[3] - mean) * rstd * gg.w + bbv.w;
    ((float4*)(out + t * DIM))[tid] = ov;

    __nv_bfloat16 h0 = __float2bfloat16_rn(ov.x), h1 = __float2bfloat16_rn(ov.y);
    __nv_bfloat16 h2 = __float2bfloat16_rn(ov.z), h3 = __float2bfloat16_rn(ov.w);
    __nv_bfloat162 H0; H0.x = h0; H0.y = h1;
    __nv_bfloat162 H1; H1.x = h2; H1.y = h3;
    __nv_bfloat162 L0, L1;
    L0.x = __float2bfloat16_rn(ov.x - __bfloat162float(h0));
    L0.y = __float2bfloat16_rn(ov.y - __bfloat162float(h1));
    L1.x = __float2bfloat16_rn(ov.z - __bfloat162float(h2));
    L1.y = __float2bfloat16_rn(ov.w - __bfloat162float(h3));
    ((__nv_bfloat162*)(outH + t * DIM))[2 * tid]     = H0;
    ((__nv_bfloat162*)(outH + t * DIM))[2 * tid + 1] = H1;
    ((__nv_bfloat162*)(outL + t * DIM))[2 * tid]     = L0;
    ((__nv_bfloat162*)(outL + t * DIM))[2 * tid + 1] = L1;
}

// ---------------- combine MoE slots + residual + LN2 -> d_out ----------------
__global__ void __launch_bounds__(256) ln2_kernel(
    const float* __restrict__ x1, const float* __restrict__ moe2,
    const float* __restrict__ g, const float* __restrict__ bt,
    float* __restrict__ out)
{
    long t  = blockIdx.x;
    int tid = threadIdx.x;
    float4 va = ((const float4*)(x1   + t * DIM))[tid];
    float4 vb = ((const float4*)(moe2 + (2 * t)     * DIM))[tid];
    float4 vc = ((const float4*)(moe2 + (2 * t + 1) * DIM))[tid];
    float v[4] = { va.x + vb.x + vc.x, va.y + vb.y + vc.y,
                   va.z + vb.z + vc.z, va.w + vb.w + vc.w };
    float s1 = v[0] + v[1] + v[2] + v[3];
    float s2 = v[0]*v[0] + v[1]*v[1] + v[2]*v[2] + v[3]*v[3];
    #pragma unroll
    for (int o2 = 16; o2 >= 1; o2 >>= 1) {
        s1 += __shfl_xor_sync(0xffffffffu, s1, o2);
        s2 += __shfl_xor_sync(0xffffffffu, s2, o2);
    }
    __shared__ float r1[8], r2[8], mv[2];
    if ((tid & 31) == 0) { r1[tid >> 5] = s1; r2[tid >> 5] = s2; }
    __syncthreads();
    if (tid == 0) {
        float A = 0.f, Bq = 0.f;
        #pragma unroll
        for (int w = 0; w < 8; w++) { A += r1[w]; Bq += r2[w]; }
        float mean = A * (1.f / DIM);
        float var  = Bq * (1.f / DIM) - mean * mean;
        mv[0] = mean; mv[1] = rsqrtf(var + 1e-5f);
    }
    __syncthreads();
    float mean = mv[0], rstd = mv[1];
    float4 gg  = ((const float4*)g)[tid];
    float4 bbv = ((const float4*)bt)[tid];
    float4 ov;
    ov.x = (v[0] - mean) * rstd * gg.x + bbv.x;
    ov.y = (v[1] - mean) * rstd * gg.y + bbv.y;
    ov.z = (v[2] - mean) * rstd * gg.z + bbv.z;
    ov.w = (v[3] - mean) * rstd * gg.w + bbv.w;
    ((float4*)(out + t * DIM))[tid] = ov;
}

// ---------------- gate: logits, softmax usage, top-2 -------------------------
__global__ void __launch_bounds__(256) gate_kernel(
    const float* __restrict__ x, const float* __restrict__ gw,
    const float* __restrict__ gb)
{
    int t = blockIdx.x;
    int w = threadIdx.x >> 5, lane = threadIdx.x & 31;
    const float* xr = x + (long)t * DIM;
    const float* wr = gw + w * DIM;
    float s = 0.f;
    for (int d = lane; d < DIM; d += 32) s += xr[d] * wr[d];
    #pragma unroll
    for (int o2 = 16; o2 >= 1; o2 >>= 1) s += __shfl_xor_sync(0xffffffffu, s, o2);
    __shared__ float lg[NEXP];
    if (lane == 0) lg[w] = s + gb[w];
    __syncthreads();
    if (threadIdx.x == 0) {
        float mx = lg[0];
        #pragma unroll
        for (int e = 1; e < NEXP; e++) mx = fmaxf(mx, lg[e]);
        float ex[NEXP], sum = 0.f;
        #pragma unroll
        for (int e = 0; e < NEXP; e++) { ex[e] = expf(lg[e] - mx); sum += ex[e]; }
        float inv = 1.f / sum;
        #pragma unroll
        for (int e = 0; e < NEXP; e++) atomicAdd(&g_usage[e], ex[e] * inv);
        int e0 = 0;
        #pragma unroll
        for (int e = 1; e < NEXP; e++) if (lg[e] > lg[e0]) e0 = e;
        int e1 = -1;
        #pragma unroll
        for (int e = 0; e < NEXP; e++)
            if (e != e0 && (e1 < 0 || lg[e] > lg[e1])) e1 = e;
        float z  = expf(lg[e1] - lg[e0]);
        float p0 = 1.f / (1.f + z);
        g_tidx[2 * t]     = e0;  g_tidx[2 * t + 1]  = e1;
        g_tprob[2 * t]    = p0;  g_tprob[2 * t + 1] = z * p0;
        atomicAdd(&g_count[e0], 1);
        atomicAdd(&g_count[e1], 1);
    }
}

__global__ void k_offsets() {
    if (threadIdx.x == 0) {
        int a = 0;
        for (int e = 0; e < NEXP; e++) { g_off[e] = a; a += g_count[e]; }
    }
}

__global__ void k_fill() {
    int t = blockIdx.x * blockDim.x + threadIdx.x;
    if (t < TOK) {
        #pragma unroll
        for (int k = 0; k < 2; k++) {
            int e   = g_tidx[2 * t + k];
            int pos = atomicAdd(&g_fill[e], 1);
            g_list[g_off[e] + pos] = 2 * t + k;
        }
    }
}

__global__ void k_aux(float* out) {
    float s = 0.f;
    #pragma unroll
    for (int e = 0; e < NEXP; e++) {
        float u = g_usage[e] * (1.f / TOK);
        s += u * u;
    }
    out[(size_t)TOK * DIM] = (float)NEXP * s;
}

// ---------------- launch ----------------
extern "C" void kernel_launch(void* const* d_in, const int* in_sizes, int n_in,
                              void* d_out, int out_size)
{
    (void)in_sizes; (void)n_in;
    const float* src  = (const float*)d_in[0];
    const float* ipw  = (const float*)d_in[1];
    const float* ipb  = (const float*)d_in[2];
    const float* outw = (const float*)d_in[3];
    const float* outb = (const float*)d_in[4];
    const float* gw   = (const float*)d_in[5];
    const float* gb   = (const float*)d_in[6];
    const float* w1   = (const float*)d_in[7];
    const float* b1   = (const float*)d_in[8];
    const float* w2   = (const float*)d_in[9];
    const float* b2   = (const float*)d_in[10];
    const float* ln1g = (const float*)d_in[11];
    const float* ln1b = (const float*)d_in[12];
    const float* ln2g = (const float*)d_in[13];
    const float* ln2b = (const float*)d_in[14];
    float* out = (float*)d_out;

    float *p_proj, *p_x1, *p_moe2;
    cudaGetSymbolAddress((void**)&p_proj, g_proj);
    cudaGetSymbolAddress((void**)&p_x1,   g_x1);
    cudaGetSymbolAddress((void**)&p_moe2, g_moe2);
    __nv_bfloat16 *qkvH, *qkvL, *srcH, *srcL, *attnH, *attnL, *x1H, *x1L, *hH, *hL;
    __nv_bfloat16 *ipwH, *ipwL, *outwH, *outwL, *w1H, *w1L, *w2H, *w2L;
    cudaGetSymbolAddress((void**)&qkvH,  g_qkvH);
    cudaGetSymbolAddress((void**)&qkvL,  g_qkvL);
    cudaGetSymbolAddress((void**)&srcH,  g_srcH);
    cudaGetSymbolAddress((void**)&srcL,  g_srcL);
    cudaGetSymbolAddress((void**)&attnH, g_attnH);
    cudaGetSymbolAddress((void**)&attnL, g_attnL);
    cudaGetSymbolAddress((void**)&x1H,   g_x1H);
    cudaGetSymbolAddress((void**)&x1L,   g_x1L);
    cudaGetSymbolAddress((void**)&hH,    g_hH);
    cudaGetSymbolAddress((void**)&hL,    g_hL);
    cudaGetSymbolAddress((void**)&ipwH,  g_ipwH);
    cudaGetSymbolAddress((void**)&ipwL,  g_ipwL);
    cudaGetSymbolAddress((void**)&outwH, g_outwH);
    cudaGetSymbolAddress((void**)&outwL, g_outwL);
    cudaGetSymbolAddress((void**)&w1H,   g_w1H);
    cudaGetSymbolAddress((void**)&w1L,   g_w1L);
    cudaGetSymbolAddress((void**)&w2H,   g_w2H);
    cudaGetSymbolAddress((void**)&w2L,   g_w2L);

    cudaFuncSetAttribute(attn_mma,
                         cudaFuncAttributeMaxDynamicSharedMemorySize, AT_SMEM);
    cudaFuncSetAttribute(mma_gemm<0>,
                         cudaFuncAttributeMaxDynamicSharedMemorySize, SM_TOTAL);
    cudaFuncSetAttribute(mma_gemm<1>,
                         cudaFuncAttributeMaxDynamicSharedMemorySize, SM_TOTAL);
    cudaFuncSetAttribute(mma_gemm<2>,
                         cudaFuncAttributeMaxDynamicSharedMemorySize, SM_TOTAL);
    cudaFuncSetAttribute(mma_gemm<3>,
                         cudaFuncAttributeMaxDynamicSharedMemorySize, SM_TOTAL);

    // 0) per-replay init + operand plane preparation
    k_init<<<1, 32>>>();
    {
        long n;
        n = (long)TOK * DIM / 4;
        k_conv<<<(int)((n + 255) / 256), 256>>>(src, srcH, srcL, n);
        n = (long)QKVD * DIM / 4;
        k_conv<<<(int)((n + 255) / 256), 256>>>(ipw, ipwH, ipwL, n);
        n = (long)DIM * DIM / 4;
        k_conv<<<(int)((n + 255) / 256), 256>>>(outw, outwH, outwL, n);
        n = (long)NEXP * FDIM * DIM / 4;
        k_conv<<<(int)((n + 255) / 256), 256>>>(w1, w1H, w1L, n);
        n = (long)NEXP * DIM * FDIM / 4;
        k_conv<<<(int)((n + 255) / 256), 256>>>(w2, w2H, w2L, n);
    }

    // 1) QKV projection -> hi/lo planes, Q columns pre-scaled by 1/8
    mma_gemm<3><<<dim3(QKVD / 128, TOK / 128, 1), 256, SM_TOTAL>>>(
        srcH, srcL, ipwH, ipwL, ipb, 0, qkvH, qkvL, TOK, QKVD, DIM, 0, 0);

    // 2) tensor-core flash attention -> attn hi/lo planes
    attn_mma<<<dim3(SS / 128, BB * NHEAD), 256, AT_SMEM>>>(qkvH, qkvL, attnH, attnL);

    // 3) output projection (fp32 out for LN)
    mma_gemm<0><<<dim3(DIM / 128, TOK / 128, 1), 256, SM_TOTAL>>>(
        attnH, attnL, outwH, outwL, outb, p_proj, 0, 0, TOK, DIM, DIM, 0, 0);

    // 4) x1 = LN(src + attn_out); also emit x1 planes
    ln_res_kernel<<<TOK, 256>>>(p_proj, src, ln1g, ln1b, p_x1, x1H, x1L);

    // 5) gating
    gate_kernel<<<TOK, 256>>>(p_x1, gw, gb);
    k_offsets<<<1, 32>>>();
    k_fill<<<TOK / 256, 256>>>();

    // 6) expert GEMM1: h = gelu(x1 @ w1[e]^T + b1[e]) -> hi/lo planes
    mma_gemm<1><<<dim3(FDIM / 128, TOK / 128, NEXP), 256, SM_TOTAL>>>(
        x1H, x1L, w1H, w1L, b1, 0, hH, hL,
        TOK, FDIM, DIM, (long)FDIM * DIM, FDIM);

    // 7) expert GEMM2: eo = (h @ w2[e]^T + b2[e]) * prob -> fp32 scatter
    mma_gemm<2><<<dim3(DIM / 128, TOK / 128, NEXP), 256, SM_TOTAL>>>(
        hH, hL, w2H, w2L, b2, p_moe2, 0, 0,
        TOK, DIM, FDIM, (long)DIM * FDIM, DIM);

    // 8) out = LN(x1 + moe_out)
    ln2_kernel<<<TOK, 256>>>(p_x1, p_moe2, ln2g, ln2b, out);

    // 9) aux loss
    if (out_size > TOK * DIM) k_aux<<<1, 1>>>(out);
}